// round 7
// baseline (speedup 1.0000x reference)
#include <cuda_runtime.h>
#include <cuda_bf16.h>
#include <cstdint>

#define DIM 128
#define NODES_MAX 50048
#define EDGES_MAX 800000

typedef __nv_bfloat16 bf16;
typedef __nv_bfloat162 bf162;

// ---------------- device scratch (allocation-free rule) ----------------
__device__ int   g_deg_i[NODES_MAX];
__device__ int   g_rowptr[NODES_MAX + 1];
__device__ int   g_csr[EDGES_MAX];
__device__ float g_invdeg[NODES_MAX];
__device__ __align__(16) bf16  g_xh[(size_t)NODES_MAX * DIM];  // split-bf16 activations
__device__ __align__(16) bf16  g_xl[(size_t)NODES_MAX * DIM];
__device__ __align__(16) bf16  g_aggh[(size_t)NODES_MAX * DIM];
__device__ __align__(16) bf16  g_aggl[(size_t)NODES_MAX * DIM];
__device__ __align__(16) bf16  g_hh[(size_t)NODES_MAX * DIM];
__device__ __align__(16) bf16  g_hl[(size_t)NODES_MAX * DIM];
__device__ __align__(16) bf16  g_wth[6 * 16384];               // transposed [N][K] weight hi
__device__ __align__(16) bf16  g_wtl[6 * 16384];               // lo parts

// ---------------- PTX helpers (sm_80-baseline features only) ----------------
__device__ __forceinline__ uint32_t smem_to_u32(const void* p) {
    uint32_t a;
    asm("{ .reg .u64 t; cvta.to.shared.u64 t, %1; cvt.u32.u64 %0, t; }" : "=r"(a) : "l"(p));
    return a;
}
__device__ __forceinline__ void ldsm_x4(uint32_t* r, uint32_t addr) {
    asm volatile("ldmatrix.sync.aligned.m8n8.x4.shared.b16 {%0,%1,%2,%3}, [%4];"
                 : "=r"(r[0]), "=r"(r[1]), "=r"(r[2]), "=r"(r[3]) : "r"(addr));
}
__device__ __forceinline__ void mma_bf16(float* d, const uint32_t* a, const uint32_t* b) {
    asm volatile(
        "mma.sync.aligned.m16n8k16.row.col.f32.bf16.bf16.f32 "
        "{%0,%1,%2,%3}, {%4,%5,%6,%7}, {%8,%9}, {%0,%1,%2,%3};"
        : "+f"(d[0]), "+f"(d[1]), "+f"(d[2]), "+f"(d[3])
        : "r"(a[0]), "r"(a[1]), "r"(a[2]), "r"(a[3]), "r"(b[0]), "r"(b[1]));
}
__device__ __forceinline__ void cp16(uint32_t d, const void* g) {
    asm volatile("cp.async.cg.shared.global [%0], [%1], 16;" :: "r"(d), "l"(g));
}
__device__ __forceinline__ void zero16(uint32_t d) {
    asm volatile("st.shared.v4.b32 [%0], {%1,%1,%1,%1};" :: "r"(d), "r"(0u));
}
#define CP_COMMIT() asm volatile("cp.async.commit_group;" ::: "memory")
#define CP_WAIT1()  asm volatile("cp.async.wait_group 1;" ::: "memory")
#define CP_WAIT0()  asm volatile("cp.async.wait_group 0;" ::: "memory")

// ---------------- CSR build ----------------
__global__ void zero_int_kernel(int* __restrict__ p, int n) {
    int i = blockIdx.x * blockDim.x + threadIdx.x;
    if (i < n) p[i] = 0;
}
__global__ void deg_kernel(const int* __restrict__ dst, int* __restrict__ deg, int E) {
    int e = blockIdx.x * blockDim.x + threadIdx.x;
    if (e < E) atomicAdd(&deg[dst[e]], 1);
}
// thread-coarsened single-block exclusive scan; also emits invdeg
__global__ void __launch_bounds__(1024)
scan_kernel(const int* __restrict__ cnt, int* __restrict__ rowptr,
            float* __restrict__ inv, int n) {
    __shared__ int wsum[32];
    const int tid = threadIdx.x;
    const int CH = (n + 1023) / 1024;
    const int base = tid * CH;
    int s = 0;
    for (int j = 0; j < CH; ++j) { int i = base + j; if (i < n) s += __ldg(cnt + i); }
    int v = s;
#pragma unroll
    for (int o = 1; o < 32; o <<= 1) { int u = __shfl_up_sync(~0u, v, o); if ((tid & 31) >= o) v += u; }
    if ((tid & 31) == 31) wsum[tid >> 5] = v;
    __syncthreads();
    if (tid < 32) {
        int w = wsum[tid];
#pragma unroll
        for (int o = 1; o < 32; o <<= 1) { int u = __shfl_up_sync(~0u, w, o); if (tid >= o) w += u; }
        wsum[tid] = w;
    }
    __syncthreads();
    int run = (v - s) + ((tid >= 32) ? wsum[(tid >> 5) - 1] : 0);
    for (int j = 0; j < CH; ++j) {
        int i = base + j;
        if (i < n) {
            int c = __ldg(cnt + i);
            run += c;
            rowptr[i + 1] = run;
            inv[i] = 1.0f / (float)max(c, 1);
        }
    }
    if (tid == 0) rowptr[0] = 0;
}
// fill via atomic countdown on deg (restores deg to all-zero for the next replay)
__global__ void fill_csr_kernel(const int* __restrict__ src, const int* __restrict__ dst,
                                const int* __restrict__ rowptr, int* __restrict__ deg,
                                int* __restrict__ csr, int E) {
    int e = blockIdx.x * blockDim.x + threadIdx.x;
    if (e < E) {
        int d = dst[e];
        int cnt = atomicAdd(&deg[d], -1);
        csr[rowptr[d] + cnt - 1] = src[e];
    }
}

// ---------------- split conversions ----------------
__device__ __forceinline__ void split2(float v0, float v1, bf162& hi, bf162& lo) {
    bf16 h0 = __float2bfloat16(v0), h1 = __float2bfloat16(v1);
    bf16 l0 = __float2bfloat16(v0 - __bfloat162float(h0));
    bf16 l1 = __float2bfloat16(v1 - __bfloat162float(h1));
    hi = __halves2bfloat162(h0, h1);
    lo = __halves2bfloat162(l0, l1);
}
__global__ void split_kernel(const float* __restrict__ x, bf16* __restrict__ h,
                             bf16* __restrict__ l, int n2) {
    int i = blockIdx.x * blockDim.x + threadIdx.x;
    if (i < n2) {
        float2 v = reinterpret_cast<const float2*>(x)[i];
        bf162 hi, lo;
        split2(v.x, v.y, hi, lo);
        reinterpret_cast<bf162*>(h)[i] = hi;
        reinterpret_cast<bf162*>(l)[i] = lo;
    }
}
__global__ void wsplit_kernel(const float* W1s, const float* W1n, const float* W2s,
                              const float* W2n, const float* W3s, const float* W3n,
                              bf16* __restrict__ th, bf16* __restrict__ tl) {
    int i = blockIdx.x * blockDim.x + threadIdx.x;
    int m, off;
    if (i < 4 * 16384) { m = i / 16384; off = i % 16384; }
    else {
        int j = i - 4 * 16384;
        if (j >= 2 * 8192) return;
        m = 4 + j / 8192; off = j % 8192;
    }
    const float* src = (m == 0) ? W1s : (m == 1) ? W1n : (m == 2) ? W2s
                     : (m == 3) ? W2n : (m == 4) ? W3s : W3n;
    int Ncols = (m < 4) ? 128 : 64;
    int nn = off / 128, kk = off % 128;
    float v = src[kk * Ncols + nn];
    bf16 h = __float2bfloat16(v);
    th[m * 16384 + off] = h;
    tl[m * 16384 + off] = __float2bfloat16(v - __bfloat162float(h));
}

// ------- atomic-free mean aggregation over split-bf16 features (halved gather traffic) -------
// feature row r reconstructed as float(fh[r])+float(fl[r]); sums in fp32; emits split bf16.
__global__ void __launch_bounds__(256)
agg_kernel(const bf16* __restrict__ fh, const bf16* __restrict__ fl,
           const int* __restrict__ rowptr, const int* __restrict__ csr,
           const float* __restrict__ invdeg,
           bf16* __restrict__ aggh, bf16* __restrict__ aggl, int n) {
    long long t = (long long)blockIdx.x * blockDim.x + threadIdx.x;
    int v = (int)(t >> 5);
    if (v >= n) return;
    int lane = (int)(t & 31);
    const int co = lane * 4;   // 4 bf16 columns per lane (8B per array)

    int beg = __ldg(rowptr + v);
    int end = __ldg(rowptr + v + 1);

    float ax = 0.f, ay = 0.f, az = 0.f, aw = 0.f;
    int i = beg;
    for (; i + 2 <= end; i += 2) {
        int s0 = __ldg(csr + i + 0);
        int s1 = __ldg(csr + i + 1);
        uint2 h0 = *reinterpret_cast<const uint2*>(fh + (size_t)s0 * DIM + co);
        uint2 l0 = *reinterpret_cast<const uint2*>(fl + (size_t)s0 * DIM + co);
        uint2 h1 = *reinterpret_cast<const uint2*>(fh + (size_t)s1 * DIM + co);
        uint2 l1 = *reinterpret_cast<const uint2*>(fl + (size_t)s1 * DIM + co);
        float2 a0 = __bfloat1622float2(*reinterpret_cast<bf162*>(&h0.x));
        float2 b0 = __bfloat1622float2(*reinterpret_cast<bf162*>(&h0.y));
        float2 c0 = __bfloat1622float2(*reinterpret_cast<bf162*>(&l0.x));
        float2 d0 = __bfloat1622float2(*reinterpret_cast<bf162*>(&l0.y));
        float2 a1 = __bfloat1622float2(*reinterpret_cast<bf162*>(&h1.x));
        float2 b1 = __bfloat1622float2(*reinterpret_cast<bf162*>(&h1.y));
        float2 c1 = __bfloat1622float2(*reinterpret_cast<bf162*>(&l1.x));
        float2 d1 = __bfloat1622float2(*reinterpret_cast<bf162*>(&l1.y));
        ax += (a0.x + c0.x) + (a1.x + c1.x);
        ay += (a0.y + c0.y) + (a1.y + c1.y);
        az += (b0.x + d0.x) + (b1.x + d1.x);
        aw += (b0.y + d0.y) + (b1.y + d1.y);
    }
    for (; i < end; ++i) {
        int s0 = __ldg(csr + i);
        uint2 h0 = *reinterpret_cast<const uint2*>(fh + (size_t)s0 * DIM + co);
        uint2 l0 = *reinterpret_cast<const uint2*>(fl + (size_t)s0 * DIM + co);
        float2 a0 = __bfloat1622float2(*reinterpret_cast<bf162*>(&h0.x));
        float2 b0 = __bfloat1622float2(*reinterpret_cast<bf162*>(&h0.y));
        float2 c0 = __bfloat1622float2(*reinterpret_cast<bf162*>(&l0.x));
        float2 d0 = __bfloat1622float2(*reinterpret_cast<bf162*>(&l0.y));
        ax += a0.x + c0.x; ay += a0.y + c0.y;
        az += b0.x + d0.x; aw += b0.y + d0.y;
    }
    float sc = __ldg(invdeg + v);
    bf162 h01, l01, h23, l23;
    split2(ax * sc, ay * sc, h01, l01);
    split2(az * sc, aw * sc, h23, l23);
    reinterpret_cast<bf162*>(aggh + (size_t)v * DIM)[lane * 2 + 0] = h01;
    reinterpret_cast<bf162*>(aggh + (size_t)v * DIM)[lane * 2 + 1] = h23;
    reinterpret_cast<bf162*>(aggl + (size_t)v * DIM)[lane * 2 + 0] = l01;
    reinterpret_cast<bf162*>(aggl + (size_t)v * DIM)[lane * 2 + 1] = l23;
}

// ---------------- HMMA fused SAGE layer: persistent, cp.async double-buffered ----------------
// smem: [stage0: 4 x 8KB act tiles][stage1] @0/32768; weights @65536 (4 x NOUT*256B).
__device__ __forceinline__ void load_swz(const bf16* __restrict__ g, char* __restrict__ s,
                                         int rows, int t) {
    for (int i = t; i < rows * 16; i += 256) {
        int row = i >> 4, c = i & 15;
        uint4 v = *reinterpret_cast<const uint4*>(g + (size_t)row * 128 + c * 8);
        *reinterpret_cast<uint4*>(s + (size_t)row * 256 + ((c ^ (row & 7)) << 4)) = v;
    }
}
__device__ __forceinline__ void issue_tile(const bf16* __restrict__ xh, const bf16* __restrict__ xl,
                                           const bf16* __restrict__ gh, const bf16* __restrict__ gl,
                                           int row0, int n, uint32_t stage, int t) {
    int valid = min(32, n - row0);
    for (int i = t; i < 512; i += 256) {
        int row = i >> 4, c = i & 15;
        uint32_t off = (uint32_t)row * 256u + (uint32_t)((c ^ (row & 7)) << 4);
        size_t goff = (size_t)(row0 + row) * 128 + c * 8;
        if (row < valid) {
            cp16(stage + off,          xh + goff);
            cp16(stage + 8192u + off,  xl + goff);
            cp16(stage + 16384u + off, gh + goff);
            cp16(stage + 24576u + off, gl + goff);
        } else {
            zero16(stage + off);          zero16(stage + 8192u + off);
            zero16(stage + 16384u + off); zero16(stage + 24576u + off);
        }
    }
}

// RELU_SPLIT=true: h = relu(X@Ws + b + AGG@Wn) -> bf16 hi/lo only (oh/ol)
// RELU_SPLIT=false: out = X@Ws + b + AGG@Wn   -> fp32 (outf)
template <int NOUT, bool RELU_SPLIT>
__global__ void __launch_bounds__(256, 1)
gemm_kernel(const bf16* __restrict__ xh, const bf16* __restrict__ xl,
            const bf16* __restrict__ gh, const bf16* __restrict__ gl,
            const bf16* __restrict__ wsh, const bf16* __restrict__ wsl,
            const bf16* __restrict__ wnh, const bf16* __restrict__ wnl,
            const float* __restrict__ bias, float* __restrict__ outf,
            bf16* __restrict__ oh, bf16* __restrict__ ol, int n, int ntiles) {
    extern __shared__ char smem[];
    constexpr int NB = NOUT * 256;   // bytes per weight tile
    constexpr int WBASE = 65536;
    constexpr int NPW = NOUT / 4;    // cols per warp
    constexpr int NT = NPW / 8;      // 8-col acc tiles per warp
    const uint32_t sb = smem_to_u32(smem);
    const uint32_t wb = sb + WBASE;
    const int t = threadIdx.x, lane = t & 31, wid = t >> 5;

    load_swz(wsh, smem + WBASE,          NOUT, t);
    load_swz(wsl, smem + WBASE + NB,     NOUT, t);
    load_swz(wnh, smem + WBASE + 2 * NB, NOUT, t);
    load_swz(wnl, smem + WBASE + 3 * NB, NOUT, t);

    const int rhalf = (wid & 1) * 16;
    const int n0 = (wid >> 1) * NPW;
    const int arowl = rhalf + (lane & 15);
    const int akh = lane >> 4;
    const int browl = ((lane >> 4) << 3) + (lane & 7);
    const int bkh = (lane >> 3) & 1;

    float breg[NT][2];
#pragma unroll
    for (int nt = 0; nt < NT; ++nt) {
        int c = n0 + nt * 8 + (lane & 3) * 2;
        breg[nt][0] = __ldg(bias + c);
        breg[nt][1] = __ldg(bias + c + 1);
    }

    int tile = blockIdx.x, buf = 0;
    issue_tile(xh, xl, gh, gl, tile * 32, n, sb, t);
    CP_COMMIT();

    for (; tile < ntiles; tile += gridDim.x) {
        const int nxt = tile + gridDim.x;
        if (nxt < ntiles) {
            issue_tile(xh, xl, gh, gl, nxt * 32, n, sb + (uint32_t)(buf ^ 1) * 32768u, t);
            CP_COMMIT();
            CP_WAIT1();
        } else {
            CP_WAIT0();
        }
        __syncthreads();

        const uint32_t ab = sb + (uint32_t)buf * 32768u;
        float acc[NT][4];
#pragma unroll
        for (int q = 0; q < NT; ++q) { acc[q][0] = acc[q][1] = acc[q][2] = acc[q][3] = 0.f; }

#pragma unroll
        for (int ks = 0; ks < 8; ++ks) {
            uint32_t ac = (uint32_t)((2 * ks + akh) ^ (arowl & 7));
            uint32_t aoff = (uint32_t)arowl * 256u + (ac << 4);
            uint32_t Ah[4], Al[4], Gh[4], Gl[4];
            ldsm_x4(Ah, ab + aoff);
            ldsm_x4(Al, ab + 8192u + aoff);
            ldsm_x4(Gh, ab + 16384u + aoff);
            ldsm_x4(Gl, ab + 24576u + aoff);
#pragma unroll
            for (int np = 0; np < NT / 2; ++np) {
                int brow = n0 + np * 16 + browl;
                uint32_t bc = (uint32_t)((2 * ks + bkh) ^ (brow & 7));
                uint32_t boff = (uint32_t)brow * 256u + (bc << 4);
                uint32_t Bsh[4], Bsl[4], Bnh[4], Bnl[4];
                ldsm_x4(Bsh, wb + boff);
                ldsm_x4(Bsl, wb + (uint32_t)NB + boff);
                ldsm_x4(Bnh, wb + (uint32_t)(2 * NB) + boff);
                ldsm_x4(Bnl, wb + (uint32_t)(3 * NB) + boff);
                float* a0 = acc[np * 2];
                float* a1 = acc[np * 2 + 1];
                mma_bf16(a0, Ah, Bsh);  mma_bf16(a1, Ah, Bsh + 2);
                mma_bf16(a0, Gh, Bnh);  mma_bf16(a1, Gh, Bnh + 2);
                mma_bf16(a0, Al, Bsh);  mma_bf16(a1, Al, Bsh + 2);
                mma_bf16(a0, Gl, Bnh);  mma_bf16(a1, Gl, Bnh + 2);
                mma_bf16(a0, Ah, Bsl);  mma_bf16(a1, Ah, Bsl + 2);
                mma_bf16(a0, Gh, Bnl);  mma_bf16(a1, Gh, Bnl + 2);
            }
        }

        const int r0 = tile * 32 + rhalf + (lane >> 2);
        const int r1 = r0 + 8;
#pragma unroll
        for (int nt = 0; nt < NT; ++nt) {
            int c = n0 + nt * 8 + (lane & 3) * 2;
            float v0 = acc[nt][0] + breg[nt][0], v1 = acc[nt][1] + breg[nt][1];
            float v2 = acc[nt][2] + breg[nt][0], v3 = acc[nt][3] + breg[nt][1];
            if (RELU_SPLIT) {
                v0 = fmaxf(v0, 0.f); v1 = fmaxf(v1, 0.f);
                v2 = fmaxf(v2, 0.f); v3 = fmaxf(v3, 0.f);
            }
            if (r0 < n) {
                if (RELU_SPLIT) {
                    bf162 hi, lo;
                    split2(v0, v1, hi, lo);
                    *reinterpret_cast<bf162*>(oh + (size_t)r0 * NOUT + c) = hi;
                    *reinterpret_cast<bf162*>(ol + (size_t)r0 * NOUT + c) = lo;
                } else {
                    *reinterpret_cast<float2*>(outf + (size_t)r0 * NOUT + c) = make_float2(v0, v1);
                }
            }
            if (r1 < n) {
                if (RELU_SPLIT) {
                    bf162 hi, lo;
                    split2(v2, v3, hi, lo);
                    *reinterpret_cast<bf162*>(oh + (size_t)r1 * NOUT + c) = hi;
                    *reinterpret_cast<bf162*>(ol + (size_t)r1 * NOUT + c) = lo;
                } else {
                    *reinterpret_cast<float2*>(outf + (size_t)r1 * NOUT + c) = make_float2(v2, v3);
                }
            }
        }
        __syncthreads();
        buf ^= 1;
    }
}

// ---------------- launch ----------------
extern "C" void kernel_launch(void* const* d_in, const int* in_sizes, int n_in,
                              void* d_out, int out_size) {
    const float* x   = (const float*)d_in[0];
    const int*   src = (const int*)d_in[1];
    const int*   dst = (const int*)d_in[2];
    const float* Ws1 = (const float*)d_in[3];
    const float* b1  = (const float*)d_in[4];
    const float* Wn1 = (const float*)d_in[5];
    const float* Ws2 = (const float*)d_in[6];
    const float* b2  = (const float*)d_in[7];
    const float* Wn2 = (const float*)d_in[8];
    const float* Ws3 = (const float*)d_in[9];
    const float* b3  = (const float*)d_in[10];
    const float* Wn3 = (const float*)d_in[11];

    const int N = in_sizes[0] / DIM;
    const int E = in_sizes[1];
    float* out = (float*)d_out;

    int *deg_i, *rowptr, *csr;
    float *invdeg;
    bf16 *xh, *xl, *aggh, *aggl, *hh, *hl, *wth, *wtl;
    cudaGetSymbolAddress((void**)&deg_i,  g_deg_i);
    cudaGetSymbolAddress((void**)&rowptr, g_rowptr);
    cudaGetSymbolAddress((void**)&csr,    g_csr);
    cudaGetSymbolAddress((void**)&invdeg, g_invdeg);
    cudaGetSymbolAddress((void**)&xh,     g_xh);
    cudaGetSymbolAddress((void**)&xl,     g_xl);
    cudaGetSymbolAddress((void**)&aggh,   g_aggh);
    cudaGetSymbolAddress((void**)&aggl,   g_aggl);
    cudaGetSymbolAddress((void**)&hh,     g_hh);
    cudaGetSymbolAddress((void**)&hl,     g_hl);
    cudaGetSymbolAddress((void**)&wth,    g_wth);
    cudaGetSymbolAddress((void**)&wtl,    g_wtl);

    const int SM128 = 65536 + 4 * 128 * 256;  // 196608 B
    const int SM64  = 65536 + 4 * 64 * 256;   // 131072 B
    cudaFuncSetAttribute(gemm_kernel<128, true>,
                         cudaFuncAttributeMaxDynamicSharedMemorySize, SM128);
    cudaFuncSetAttribute(gemm_kernel<64, false>,
                         cudaFuncAttributeMaxDynamicSharedMemorySize, SM64);

    const int nb_nodes = (N + 255) / 256;
    const int nb_edges = (E + 255) / 256;
    const int nb_agg   = (int)(((long long)N * 32 + 255) / 256);
    const int ntiles   = (N + 31) / 32;
    const int GRID     = 152;

    // --- CSR build ---
    zero_int_kernel<<<nb_nodes, 256>>>(deg_i, N);
    deg_kernel<<<nb_edges, 256>>>(dst, deg_i, E);
    scan_kernel<<<1, 1024>>>(deg_i, rowptr, invdeg, N);
    fill_csr_kernel<<<nb_edges, 256>>>(src, dst, rowptr, deg_i, csr, E);

    // --- input/weight splits ---
    split_kernel<<<(N * DIM / 2 + 255) / 256, 256>>>(x, xh, xl, N * DIM / 2);
    wsplit_kernel<<<(81920 + 255) / 256, 256>>>(Ws1, Wn1, Ws2, Wn2, Ws3, Wn3, wth, wtl);

    // --- Layer 1: x -> h (bf16 pair) ---
    agg_kernel<<<nb_agg, 256>>>(xh, xl, rowptr, csr, invdeg, aggh, aggl, N);
    gemm_kernel<128, true><<<GRID, 256, SM128>>>(
        xh, xl, aggh, aggl,
        wth + 0 * 16384, wtl + 0 * 16384, wth + 1 * 16384, wtl + 1 * 16384,
        b1, nullptr, hh, hl, N, ntiles);

    // --- Layer 2: h -> h ---
    agg_kernel<<<nb_agg, 256>>>(hh, hl, rowptr, csr, invdeg, aggh, aggl, N);
    gemm_kernel<128, true><<<GRID, 256, SM128>>>(
        hh, hl, aggh, aggl,
        wth + 2 * 16384, wtl + 2 * 16384, wth + 3 * 16384, wtl + 3 * 16384,
        b2, nullptr, hh, hl, N, ntiles);

    // --- Layer 3: h -> out (mean_agg commutes with the linear map) ---
    agg_kernel<<<nb_agg, 256>>>(hh, hl, rowptr, csr, invdeg, aggh, aggl, N);
    gemm_kernel<64, false><<<GRID, 256, SM64>>>(
        hh, hl, aggh, aggl,
        wth + 4 * 16384, wtl + 4 * 16384, wth + 5 * 16384, wtl + 5 * 16384,
        b3, out, nullptr, nullptr, N, ntiles);
}

// round 8
// speedup vs baseline: 1.0613x; 1.0613x over previous
#include <cuda_runtime.h>
#include <cuda_bf16.h>
#include <cstdint>

#define DIM 128
#define NODES_MAX 50048
#define EDGES_MAX 800000

typedef __nv_bfloat16 bf16;
typedef __nv_bfloat162 bf162;

// ---------------- device scratch (allocation-free rule) ----------------
__device__ int   g_deg_i[NODES_MAX];
__device__ int   g_rowptr[NODES_MAX + 1];
__device__ int   g_csr[EDGES_MAX];
__device__ float g_invdeg[NODES_MAX];
__device__ __align__(16) float g_h[(size_t)NODES_MAX * DIM];   // fp32 activations (agg input)
__device__ __align__(16) bf16  g_xh[(size_t)NODES_MAX * DIM];  // split-bf16 GEMM inputs
__device__ __align__(16) bf16  g_xl[(size_t)NODES_MAX * DIM];
__device__ __align__(16) bf16  g_aggh[(size_t)NODES_MAX * DIM];
__device__ __align__(16) bf16  g_aggl[(size_t)NODES_MAX * DIM];
__device__ __align__(16) bf16  g_hh[(size_t)NODES_MAX * DIM];
__device__ __align__(16) bf16  g_hl[(size_t)NODES_MAX * DIM];
__device__ __align__(16) bf16  g_wth[6 * 16384];               // transposed [N][K] weight hi
__device__ __align__(16) bf16  g_wtl[6 * 16384];               // lo parts

// ---------------- PTX helpers (sm_80-baseline features only) ----------------
__device__ __forceinline__ uint32_t smem_to_u32(const void* p) {
    uint32_t a;
    asm("{ .reg .u64 t; cvta.to.shared.u64 t, %1; cvt.u32.u64 %0, t; }" : "=r"(a) : "l"(p));
    return a;
}
__device__ __forceinline__ void ldsm_x4(uint32_t* r, uint32_t addr) {
    asm volatile("ldmatrix.sync.aligned.m8n8.x4.shared.b16 {%0,%1,%2,%3}, [%4];"
                 : "=r"(r[0]), "=r"(r[1]), "=r"(r[2]), "=r"(r[3]) : "r"(addr));
}
__device__ __forceinline__ void mma_bf16(float* d, const uint32_t* a, const uint32_t* b) {
    asm volatile(
        "mma.sync.aligned.m16n8k16.row.col.f32.bf16.bf16.f32 "
        "{%0,%1,%2,%3}, {%4,%5,%6,%7}, {%8,%9}, {%0,%1,%2,%3};"
        : "+f"(d[0]), "+f"(d[1]), "+f"(d[2]), "+f"(d[3])
        : "r"(a[0]), "r"(a[1]), "r"(a[2]), "r"(a[3]), "r"(b[0]), "r"(b[1]));
}
__device__ __forceinline__ void cp16(uint32_t d, const void* g) {
    asm volatile("cp.async.cg.shared.global [%0], [%1], 16;" :: "r"(d), "l"(g));
}
__device__ __forceinline__ void zero16(uint32_t d) {
    asm volatile("st.shared.v4.b32 [%0], {%1,%1,%1,%1};" :: "r"(d), "r"(0u));
}
#define CP_COMMIT() asm volatile("cp.async.commit_group;" ::: "memory")
#define CP_WAIT1()  asm volatile("cp.async.wait_group 1;" ::: "memory")
#define CP_WAIT0()  asm volatile("cp.async.wait_group 0;" ::: "memory")

// ---------------- CSR build ----------------
__global__ void zero_int_kernel(int* __restrict__ p, int n) {
    int i = blockIdx.x * blockDim.x + threadIdx.x;
    if (i < n) p[i] = 0;
}
__global__ void deg_kernel(const int* __restrict__ dst, int* __restrict__ deg, int E) {
    int e = blockIdx.x * blockDim.x + threadIdx.x;
    if (e < E) atomicAdd(&deg[dst[e]], 1);
}
__global__ void __launch_bounds__(1024)
scan_kernel(const int* __restrict__ cnt, int* __restrict__ rowptr,
            float* __restrict__ inv, int n) {
    __shared__ int wsum[32];
    const int tid = threadIdx.x;
    const int CH = (n + 1023) / 1024;
    const int base = tid * CH;
    int s = 0;
    for (int j = 0; j < CH; ++j) { int i = base + j; if (i < n) s += __ldg(cnt + i); }
    int v = s;
#pragma unroll
    for (int o = 1; o < 32; o <<= 1) { int u = __shfl_up_sync(~0u, v, o); if ((tid & 31) >= o) v += u; }
    if ((tid & 31) == 31) wsum[tid >> 5] = v;
    __syncthreads();
    if (tid < 32) {
        int w = wsum[tid];
#pragma unroll
        for (int o = 1; o < 32; o <<= 1) { int u = __shfl_up_sync(~0u, w, o); if (tid >= o) w += u; }
        wsum[tid] = w;
    }
    __syncthreads();
    int run = (v - s) + ((tid >= 32) ? wsum[(tid >> 5) - 1] : 0);
    for (int j = 0; j < CH; ++j) {
        int i = base + j;
        if (i < n) {
            int c = __ldg(cnt + i);
            run += c;
            rowptr[i + 1] = run;
            inv[i] = 1.0f / (float)max(c, 1);
        }
    }
    if (tid == 0) rowptr[0] = 0;
}
__global__ void fill_csr_kernel(const int* __restrict__ src, const int* __restrict__ dst,
                                const int* __restrict__ rowptr, int* __restrict__ deg,
                                int* __restrict__ csr, int E) {
    int e = blockIdx.x * blockDim.x + threadIdx.x;
    if (e < E) {
        int d = dst[e];
        int cnt = atomicAdd(&deg[d], -1);
        csr[rowptr[d] + cnt - 1] = src[e];
    }
}

// ---------------- split conversions ----------------
__device__ __forceinline__ void split2(float v0, float v1, bf162& hi, bf162& lo) {
    bf16 h0 = __float2bfloat16(v0), h1 = __float2bfloat16(v1);
    bf16 l0 = __float2bfloat16(v0 - __bfloat162float(h0));
    bf16 l1 = __float2bfloat16(v1 - __bfloat162float(h1));
    hi = __halves2bfloat162(h0, h1);
    lo = __halves2bfloat162(l0, l1);
}
__global__ void split_kernel(const float* __restrict__ x, bf16* __restrict__ h,
                             bf16* __restrict__ l, int n2) {
    int i = blockIdx.x * blockDim.x + threadIdx.x;
    if (i < n2) {
        float2 v = reinterpret_cast<const float2*>(x)[i];
        bf162 hi, lo;
        split2(v.x, v.y, hi, lo);
        reinterpret_cast<bf162*>(h)[i] = hi;
        reinterpret_cast<bf162*>(l)[i] = lo;
    }
}
__global__ void wsplit_kernel(const float* W1s, const float* W1n, const float* W2s,
                              const float* W2n, const float* W3s, const float* W3n,
                              bf16* __restrict__ th, bf16* __restrict__ tl) {
    int i = blockIdx.x * blockDim.x + threadIdx.x;
    int m, off;
    if (i < 4 * 16384) { m = i / 16384; off = i % 16384; }
    else {
        int j = i - 4 * 16384;
        if (j >= 2 * 8192) return;
        m = 4 + j / 8192; off = j % 8192;
    }
    const float* src = (m == 0) ? W1s : (m == 1) ? W1n : (m == 2) ? W2s
                     : (m == 3) ? W2n : (m == 4) ? W3s : W3n;
    int Ncols = (m < 4) ? 128 : 64;
    int nn = off / 128, kk = off % 128;
    float v = src[kk * Ncols + nn];
    bf16 h = __float2bfloat16(v);
    th[m * 16384 + off] = h;
    tl[m * 16384 + off] = __float2bfloat16(v - __bfloat162float(h));
}

// ---------------- atomic-free mean aggregation (fp32 gather -> split bf16 out) ----------------
__global__ void __launch_bounds__(256)
agg_kernel(const float* __restrict__ feat, const int* __restrict__ rowptr,
           const int* __restrict__ csr, const float* __restrict__ invdeg,
           bf16* __restrict__ aggh, bf16* __restrict__ aggl, int n) {
    long long t = (long long)blockIdx.x * blockDim.x + threadIdx.x;
    int v = (int)(t >> 5);
    if (v >= n) return;
    int lane = (int)(t & 31);

    int beg = __ldg(rowptr + v);
    int end = __ldg(rowptr + v + 1);

    float ax = 0.f, ay = 0.f, az = 0.f, aw = 0.f;
    int i = beg;
    for (; i + 4 <= end; i += 4) {
        int s0 = __ldg(csr + i + 0);
        int s1 = __ldg(csr + i + 1);
        int s2 = __ldg(csr + i + 2);
        int s3 = __ldg(csr + i + 3);
        float4 f0 = *reinterpret_cast<const float4*>(feat + (size_t)s0 * DIM + lane * 4);
        float4 f1 = *reinterpret_cast<const float4*>(feat + (size_t)s1 * DIM + lane * 4);
        float4 f2 = *reinterpret_cast<const float4*>(feat + (size_t)s2 * DIM + lane * 4);
        float4 f3 = *reinterpret_cast<const float4*>(feat + (size_t)s3 * DIM + lane * 4);
        ax += (f0.x + f1.x) + (f2.x + f3.x);
        ay += (f0.y + f1.y) + (f2.y + f3.y);
        az += (f0.z + f1.z) + (f2.z + f3.z);
        aw += (f0.w + f1.w) + (f2.w + f3.w);
    }
    for (; i < end; ++i) {
        int s0 = __ldg(csr + i);
        float4 f0 = *reinterpret_cast<const float4*>(feat + (size_t)s0 * DIM + lane * 4);
        ax += f0.x; ay += f0.y; az += f0.z; aw += f0.w;
    }
    float sc = __ldg(invdeg + v);
    bf162 h01, l01, h23, l23;
    split2(ax * sc, ay * sc, h01, l01);
    split2(az * sc, aw * sc, h23, l23);
    reinterpret_cast<bf162*>(aggh + (size_t)v * DIM)[lane * 2 + 0] = h01;
    reinterpret_cast<bf162*>(aggh + (size_t)v * DIM)[lane * 2 + 1] = h23;
    reinterpret_cast<bf162*>(aggl + (size_t)v * DIM)[lane * 2 + 0] = l01;
    reinterpret_cast<bf162*>(aggl + (size_t)v * DIM)[lane * 2 + 1] = l23;
}

// ------------- HMMA fused SAGE layer v2: B-fragments in registers, 64-row tiles -------------
// Weights staged through smem once, ldsm'd into per-warp register arrays; smem is then
// recycled as 2 x 64KB double-buffered activation stages (xh/xl/gh/gl @ 16KB each).
__device__ __forceinline__ void load_swz(const bf16* __restrict__ g, char* __restrict__ s,
                                         int rows, int t) {
    for (int i = t; i < rows * 16; i += 256) {
        int row = i >> 4, c = i & 15;
        uint4 v = *reinterpret_cast<const uint4*>(g + (size_t)row * 128 + c * 8);
        *reinterpret_cast<uint4*>(s + (size_t)row * 256 + ((c ^ (row & 7)) << 4)) = v;
    }
}
__device__ __forceinline__ void issue_tile(const bf16* __restrict__ xh, const bf16* __restrict__ xl,
                                           const bf16* __restrict__ gh, const bf16* __restrict__ gl,
                                           int row0, int n, uint32_t stage, int t) {
    int valid = min(64, n - row0);
    for (int i = t; i < 1024; i += 256) {    // 64 rows x 16 chunks
        int row = i >> 4, c = i & 15;
        uint32_t off = (uint32_t)row * 256u + (uint32_t)((c ^ (row & 7)) << 4);
        size_t goff = (size_t)(row0 + row) * 128 + c * 8;
        if (row < valid) {
            cp16(stage + off,          xh + goff);
            cp16(stage + 16384u + off, xl + goff);
            cp16(stage + 32768u + off, gh + goff);
            cp16(stage + 49152u + off, gl + goff);
        } else {
            zero16(stage + off);          zero16(stage + 16384u + off);
            zero16(stage + 32768u + off); zero16(stage + 49152u + off);
        }
    }
}

// NOUT=128: 8 warps x 16-col strips, each covers all 64 rows (ROWG=4).
// NOUT=64:  4 strips x 2 warp-sets; warps 0-3 rows 0-31, warps 4-7 rows 32-63 (ROWG=2).
template <int NOUT, bool RELU_SPLIT>
__global__ void __launch_bounds__(256, 1)
gemm_kernel(const bf16* __restrict__ xh, const bf16* __restrict__ xl,
            const bf16* __restrict__ gh, const bf16* __restrict__ gl,
            const bf16* __restrict__ wsh, const bf16* __restrict__ wsl,
            const bf16* __restrict__ wnh, const bf16* __restrict__ wnl,
            const float* __restrict__ bias, float* __restrict__ outf,
            bf16* __restrict__ oh, bf16* __restrict__ ol, int n, int ntiles) {
    extern __shared__ char smem[];
    constexpr int WB = NOUT * 256;                 // bytes per weight array in staging
    constexpr int ROWG = (NOUT == 128) ? 4 : 2;    // 16-row groups per warp
    const uint32_t sb = smem_to_u32(smem);
    const int t = threadIdx.x, lane = t & 31, wid = t >> 5;
    const int strip  = (NOUT == 128) ? wid : (wid & 3);
    const int rgbase = (NOUT == 128) ? 0 : (wid >> 2) * 2;
    const int n0 = strip * 16;

    // ---- stage weights in smem, hoist B fragments to registers ----
    load_swz(wsh, smem + 0 * WB, NOUT, t);
    load_swz(wsl, smem + 1 * WB, NOUT, t);
    load_swz(wnh, smem + 2 * WB, NOUT, t);
    load_swz(wnl, smem + 3 * WB, NOUT, t);
    __syncthreads();

    const int browl = ((lane >> 4) << 3) + (lane & 7);
    const int bkh = (lane >> 3) & 1;
    const int brow = n0 + browl;
    uint32_t Bsh[8][4], Bsl[8][4], Bnh[8][4], Bnl[8][4];
#pragma unroll
    for (int ks = 0; ks < 8; ++ks) {
        uint32_t bc = (uint32_t)((2 * ks + bkh) ^ (brow & 7));
        uint32_t boff = (uint32_t)brow * 256u + (bc << 4);
        ldsm_x4(Bsh[ks], sb + 0 * WB + boff);
        ldsm_x4(Bsl[ks], sb + 1 * WB + boff);
        ldsm_x4(Bnh[ks], sb + 2 * WB + boff);
        ldsm_x4(Bnl[ks], sb + 3 * WB + boff);
    }
    float breg[2][2];
#pragma unroll
    for (int nsub = 0; nsub < 2; ++nsub) {
        int c = n0 + nsub * 8 + (lane & 3) * 2;
        breg[nsub][0] = __ldg(bias + c);
        breg[nsub][1] = __ldg(bias + c + 1);
    }
    __syncthreads();   // all warps done reading weights before stages overwrite

    const int akh = lane >> 4;

    int tile = blockIdx.x, buf = 0;
    issue_tile(xh, xl, gh, gl, tile * 64, n, sb, t);
    CP_COMMIT();

    for (; tile < ntiles; tile += gridDim.x) {
        const int nxt = tile + gridDim.x;
        if (nxt < ntiles) {
            issue_tile(xh, xl, gh, gl, nxt * 64, n, sb + (uint32_t)(buf ^ 1) * 65536u, t);
            CP_COMMIT();
            CP_WAIT1();
        } else {
            CP_WAIT0();
        }
        __syncthreads();

        const uint32_t ab = sb + (uint32_t)buf * 65536u;
        float acc[ROWG][2][4];
#pragma unroll
        for (int rg = 0; rg < ROWG; ++rg)
#pragma unroll
            for (int q = 0; q < 2; ++q) {
                acc[rg][q][0] = acc[rg][q][1] = acc[rg][q][2] = acc[rg][q][3] = 0.f;
            }

#pragma unroll
        for (int ks = 0; ks < 8; ++ks) {
#pragma unroll
            for (int rg = 0; rg < ROWG; ++rg) {
                int arow = (rgbase + rg) * 16 + (lane & 15);
                uint32_t ac = (uint32_t)((2 * ks + akh) ^ (arow & 7));
                uint32_t aoff = (uint32_t)arow * 256u + (ac << 4);
                uint32_t Ah[4], Al[4], Gh[4], Gl[4];
                ldsm_x4(Ah, ab + aoff);
                ldsm_x4(Al, ab + 16384u + aoff);
                ldsm_x4(Gh, ab + 32768u + aoff);
                ldsm_x4(Gl, ab + 49152u + aoff);
                float* a0 = acc[rg][0];
                float* a1 = acc[rg][1];
                mma_bf16(a0, Ah, Bsh[ks]);  mma_bf16(a1, Ah, Bsh[ks] + 2);
                mma_bf16(a0, Gh, Bnh[ks]);  mma_bf16(a1, Gh, Bnh[ks] + 2);
                mma_bf16(a0, Al, Bsh[ks]);  mma_bf16(a1, Al, Bsh[ks] + 2);
                mma_bf16(a0, Gl, Bnh[ks]);  mma_bf16(a1, Gl, Bnh[ks] + 2);
                mma_bf16(a0, Ah, Bsl[ks]);  mma_bf16(a1, Ah, Bsl[ks] + 2);
                mma_bf16(a0, Gh, Bnl[ks]);  mma_bf16(a1, Gh, Bnl[ks] + 2);
            }
        }

        // epilogue: bias + (ReLU + bf16 re-split) + fp32 store (hidden layers need fp32 for agg)
#pragma unroll
        for (int rg = 0; rg < ROWG; ++rg) {
            const int r0 = tile * 64 + (rgbase + rg) * 16 + (lane >> 2);
            const int r1 = r0 + 8;
#pragma unroll
            for (int nsub = 0; nsub < 2; ++nsub) {
                int c = n0 + nsub * 8 + (lane & 3) * 2;
                float v0 = acc[rg][nsub][0] + breg[nsub][0];
                float v1 = acc[rg][nsub][1] + breg[nsub][1];
                float v2 = acc[rg][nsub][2] + breg[nsub][0];
                float v3 = acc[rg][nsub][3] + breg[nsub][1];
                if (RELU_SPLIT) {
                    v0 = fmaxf(v0, 0.f); v1 = fmaxf(v1, 0.f);
                    v2 = fmaxf(v2, 0.f); v3 = fmaxf(v3, 0.f);
                }
                if (r0 < n) {
                    *reinterpret_cast<float2*>(outf + (size_t)r0 * NOUT + c) = make_float2(v0, v1);
                    if (RELU_SPLIT) {
                        bf162 hi, lo;
                        split2(v0, v1, hi, lo);
                        *reinterpret_cast<bf162*>(oh + (size_t)r0 * NOUT + c) = hi;
                        *reinterpret_cast<bf162*>(ol + (size_t)r0 * NOUT + c) = lo;
                    }
                }
                if (r1 < n) {
                    *reinterpret_cast<float2*>(outf + (size_t)r1 * NOUT + c) = make_float2(v2, v3);
                    if (RELU_SPLIT) {
                        bf162 hi, lo;
                        split2(v2, v3, hi, lo);
                        *reinterpret_cast<bf162*>(oh + (size_t)r1 * NOUT + c) = hi;
                        *reinterpret_cast<bf162*>(ol + (size_t)r1 * NOUT + c) = lo;
                    }
                }
            }
        }
        __syncthreads();
        buf ^= 1;
    }
}

// ---------------- launch ----------------
extern "C" void kernel_launch(void* const* d_in, const int* in_sizes, int n_in,
                              void* d_out, int out_size) {
    const float* x   = (const float*)d_in[0];
    const int*   src = (const int*)d_in[1];
    const int*   dst = (const int*)d_in[2];
    const float* Ws1 = (const float*)d_in[3];
    const float* b1  = (const float*)d_in[4];
    const float* Wn1 = (const float*)d_in[5];
    const float* Ws2 = (const float*)d_in[6];
    const float* b2  = (const float*)d_in[7];
    const float* Wn2 = (const float*)d_in[8];
    const float* Ws3 = (const float*)d_in[9];
    const float* b3  = (const float*)d_in[10];
    const float* Wn3 = (const float*)d_in[11];

    const int N = in_sizes[0] / DIM;
    const int E = in_sizes[1];
    float* out = (float*)d_out;

    int *deg_i, *rowptr, *csr;
    float *invdeg, *h;
    bf16 *xh, *xl, *aggh, *aggl, *hh, *hl, *wth, *wtl;
    cudaGetSymbolAddress((void**)&deg_i,  g_deg_i);
    cudaGetSymbolAddress((void**)&rowptr, g_rowptr);
    cudaGetSymbolAddress((void**)&csr,    g_csr);
    cudaGetSymbolAddress((void**)&invdeg, g_invdeg);
    cudaGetSymbolAddress((void**)&h,      g_h);
    cudaGetSymbolAddress((void**)&xh,     g_xh);
    cudaGetSymbolAddress((void**)&xl,     g_xl);
    cudaGetSymbolAddress((void**)&aggh,   g_aggh);
    cudaGetSymbolAddress((void**)&aggl,   g_aggl);
    cudaGetSymbolAddress((void**)&hh,     g_hh);
    cudaGetSymbolAddress((void**)&hl,     g_hl);
    cudaGetSymbolAddress((void**)&wth,    g_wth);
    cudaGetSymbolAddress((void**)&wtl,    g_wtl);

    const int SMEM_SZ = 2 * 65536;   // 128 KB: weight staging, then 2 act stages
    cudaFuncSetAttribute(gemm_kernel<128, true>,
                         cudaFuncAttributeMaxDynamicSharedMemorySize, SMEM_SZ);
    cudaFuncSetAttribute(gemm_kernel<64, false>,
                         cudaFuncAttributeMaxDynamicSharedMemorySize, SMEM_SZ);

    const int nb_nodes = (N + 255) / 256;
    const int nb_edges = (E + 255) / 256;
    const int nb_agg   = (int)(((long long)N * 32 + 255) / 256);
    const int ntiles   = (N + 63) / 64;
    const int GRID     = 152;

    // --- CSR build ---
    zero_int_kernel<<<nb_nodes, 256>>>(deg_i, N);
    deg_kernel<<<nb_edges, 256>>>(dst, deg_i, E);
    scan_kernel<<<1, 1024>>>(deg_i, rowptr, invdeg, N);
    fill_csr_kernel<<<nb_edges, 256>>>(src, dst, rowptr, deg_i, csr, E);

    // --- input/weight splits ---
    split_kernel<<<(N * DIM / 2 + 255) / 256, 256>>>(x, xh, xl, N * DIM / 2);
    wsplit_kernel<<<(81920 + 255) / 256, 256>>>(Ws1, Wn1, Ws2, Wn2, Ws3, Wn3, wth, wtl);

    // --- Layer 1: x -> h ---
    agg_kernel<<<nb_agg, 256>>>(x, rowptr, csr, invdeg, aggh, aggl, N);
    gemm_kernel<128, true><<<GRID, 256, SMEM_SZ>>>(
        xh, xl, aggh, aggl,
        wth + 0 * 16384, wtl + 0 * 16384, wth + 1 * 16384, wtl + 1 * 16384,
        b1, h, hh, hl, N, ntiles);

    // --- Layer 2: h -> h ---
    agg_kernel<<<nb_agg, 256>>>(h, rowptr, csr, invdeg, aggh, aggl, N);
    gemm_kernel<128, true><<<GRID, 256, SMEM_SZ>>>(
        hh, hl, aggh, aggl,
        wth + 2 * 16384, wtl + 2 * 16384, wth + 3 * 16384, wtl + 3 * 16384,
        b2, h, hh, hl, N, ntiles);

    // --- Layer 3: h -> out (mean_agg commutes with the linear map) ---
    agg_kernel<<<nb_agg, 256>>>(h, rowptr, csr, invdeg, aggh, aggl, N);
    gemm_kernel<64, false><<<GRID, 256, SMEM_SZ>>>(
        hh, hl, aggh, aggl,
        wth + 4 * 16384, wtl + 4 * 16384, wth + 5 * 16384, wtl + 5 * 16384,
        b3, out, nullptr, nullptr, N, ntiles);
}

// round 9
// speedup vs baseline: 1.0922x; 1.0291x over previous
#include <cuda_runtime.h>
#include <cuda_bf16.h>
#include <cstdint>

#define DIM 128
#define NODES_MAX 50048
#define EDGES_MAX 800000

typedef __nv_bfloat16 bf16;
typedef __nv_bfloat162 bf162;

// ---------------- device scratch (allocation-free rule) ----------------
__device__ int   g_deg_i[NODES_MAX];
__device__ int   g_rowptr[NODES_MAX + 1];
__device__ int   g_csr[EDGES_MAX];
__device__ float g_invdeg[NODES_MAX];
__device__ __align__(16) float g_h[(size_t)NODES_MAX * DIM];   // fp32 activations (agg input)
__device__ __align__(16) float g_S3[(size_t)NODES_MAX * 64];   // layer-3 self partial
__device__ __align__(16) float g_P[(size_t)NODES_MAX * 64];    // layer-3 h@Wn3
__device__ __align__(16) bf16  g_xh[(size_t)NODES_MAX * DIM];  // split-bf16 GEMM inputs
__device__ __align__(16) bf16  g_xl[(size_t)NODES_MAX * DIM];
__device__ __align__(16) bf16  g_aggh[(size_t)NODES_MAX * DIM];
__device__ __align__(16) bf16  g_aggl[(size_t)NODES_MAX * DIM];
__device__ __align__(16) bf16  g_hh[(size_t)NODES_MAX * DIM];
__device__ __align__(16) bf16  g_hl[(size_t)NODES_MAX * DIM];
__device__ __align__(16) bf16  g_wth[6 * 16384];               // transposed [N][K] weight hi
__device__ __align__(16) bf16  g_wtl[6 * 16384];               // lo parts

// ---------------- PTX helpers (sm_80-baseline features only) ----------------
__device__ __forceinline__ uint32_t smem_to_u32(const void* p) {
    uint32_t a;
    asm("{ .reg .u64 t; cvta.to.shared.u64 t, %1; cvt.u32.u64 %0, t; }" : "=r"(a) : "l"(p));
    return a;
}
__device__ __forceinline__ void ldsm_x4(uint32_t* r, uint32_t addr) {
    asm volatile("ldmatrix.sync.aligned.m8n8.x4.shared.b16 {%0,%1,%2,%3}, [%4];"
                 : "=r"(r[0]), "=r"(r[1]), "=r"(r[2]), "=r"(r[3]) : "r"(addr));
}
__device__ __forceinline__ void mma_bf16(float* d, const uint32_t* a, const uint32_t* b) {
    asm volatile(
        "mma.sync.aligned.m16n8k16.row.col.f32.bf16.bf16.f32 "
        "{%0,%1,%2,%3}, {%4,%5,%6,%7}, {%8,%9}, {%0,%1,%2,%3};"
        : "+f"(d[0]), "+f"(d[1]), "+f"(d[2]), "+f"(d[3])
        : "r"(a[0]), "r"(a[1]), "r"(a[2]), "r"(a[3]), "r"(b[0]), "r"(b[1]));
}
__device__ __forceinline__ void cp16(uint32_t d, const void* g) {
    asm volatile("cp.async.cg.shared.global [%0], [%1], 16;" :: "r"(d), "l"(g));
}
__device__ __forceinline__ void zero16(uint32_t d) {
    asm volatile("st.shared.v4.b32 [%0], {%1,%1,%1,%1};" :: "r"(d), "r"(0u));
}
#define CP_COMMIT() asm volatile("cp.async.commit_group;" ::: "memory")
#define CP_WAIT1()  asm volatile("cp.async.wait_group 1;" ::: "memory")
#define CP_WAIT0()  asm volatile("cp.async.wait_group 0;" ::: "memory")

// ---------------- CSR build ----------------
__global__ void zero_int_kernel(int* __restrict__ p, int n) {
    int i = blockIdx.x * blockDim.x + threadIdx.x;
    if (i < n) p[i] = 0;
}
__global__ void deg_kernel(const int* __restrict__ dst, int* __restrict__ deg, int E) {
    int e = blockIdx.x * blockDim.x + threadIdx.x;
    if (e < E) atomicAdd(&deg[dst[e]], 1);
}
__global__ void __launch_bounds__(1024)
scan_kernel(const int* __restrict__ cnt, int* __restrict__ rowptr,
            float* __restrict__ inv, int n) {
    __shared__ int wsum[32];
    const int tid = threadIdx.x;
    const int CH = (n + 1023) / 1024;
    const int base = tid * CH;
    int s = 0;
    for (int j = 0; j < CH; ++j) { int i = base + j; if (i < n) s += __ldg(cnt + i); }
    int v = s;
#pragma unroll
    for (int o = 1; o < 32; o <<= 1) { int u = __shfl_up_sync(~0u, v, o); if ((tid & 31) >= o) v += u; }
    if ((tid & 31) == 31) wsum[tid >> 5] = v;
    __syncthreads();
    if (tid < 32) {
        int w = wsum[tid];
#pragma unroll
        for (int o = 1; o < 32; o <<= 1) { int u = __shfl_up_sync(~0u, w, o); if (tid >= o) w += u; }
        wsum[tid] = w;
    }
    __syncthreads();
    int run = (v - s) + ((tid >= 32) ? wsum[(tid >> 5) - 1] : 0);
    for (int j = 0; j < CH; ++j) {
        int i = base + j;
        if (i < n) {
            int c = __ldg(cnt + i);
            run += c;
            rowptr[i + 1] = run;
            inv[i] = 1.0f / (float)max(c, 1);
        }
    }
    if (tid == 0) rowptr[0] = 0;
}
__global__ void fill_csr_kernel(const int* __restrict__ src, const int* __restrict__ dst,
                                const int* __restrict__ rowptr, int* __restrict__ deg,
                                int* __restrict__ csr, int E) {
    int e = blockIdx.x * blockDim.x + threadIdx.x;
    if (e < E) {
        int d = dst[e];
        int cnt = atomicAdd(&deg[d], -1);
        csr[rowptr[d] + cnt - 1] = src[e];
    }
}

// ---------------- split conversions ----------------
__device__ __forceinline__ void split2(float v0, float v1, bf162& hi, bf162& lo) {
    bf16 h0 = __float2bfloat16(v0), h1 = __float2bfloat16(v1);
    bf16 l0 = __float2bfloat16(v0 - __bfloat162float(h0));
    bf16 l1 = __float2bfloat16(v1 - __bfloat162float(h1));
    hi = __halves2bfloat162(h0, h1);
    lo = __halves2bfloat162(l0, l1);
}
__global__ void split_kernel(const float* __restrict__ x, bf16* __restrict__ h,
                             bf16* __restrict__ l, int n2) {
    int i = blockIdx.x * blockDim.x + threadIdx.x;
    if (i < n2) {
        float2 v = reinterpret_cast<const float2*>(x)[i];
        bf162 hi, lo;
        split2(v.x, v.y, hi, lo);
        reinterpret_cast<bf162*>(h)[i] = hi;
        reinterpret_cast<bf162*>(l)[i] = lo;
    }
}
__global__ void wsplit_kernel(const float* W1s, const float* W1n, const float* W2s,
                              const float* W2n, const float* W3s, const float* W3n,
                              bf16* __restrict__ th, bf16* __restrict__ tl) {
    int i = blockIdx.x * blockDim.x + threadIdx.x;
    int m, off;
    if (i < 4 * 16384) { m = i / 16384; off = i % 16384; }
    else {
        int j = i - 4 * 16384;
        if (j >= 2 * 8192) return;
        m = 4 + j / 8192; off = j % 8192;
    }
    const float* src = (m == 0) ? W1s : (m == 1) ? W1n : (m == 2) ? W2s
                     : (m == 3) ? W2n : (m == 4) ? W3s : W3n;
    int Ncols = (m < 4) ? 128 : 64;
    int nn = off / 128, kk = off % 128;
    float v = src[kk * Ncols + nn];
    bf16 h = __float2bfloat16(v);
    th[m * 16384 + off] = h;
    tl[m * 16384 + off] = __float2bfloat16(v - __bfloat162float(h));
}

// ---------------- atomic-free mean aggregation (fp32 gather -> split bf16 out) ----------------
__global__ void __launch_bounds__(256)
agg_kernel(const float* __restrict__ feat, const int* __restrict__ rowptr,
           const int* __restrict__ csr, const float* __restrict__ invdeg,
           bf16* __restrict__ aggh, bf16* __restrict__ aggl, int n) {
    long long t = (long long)blockIdx.x * blockDim.x + threadIdx.x;
    int v = (int)(t >> 5);
    if (v >= n) return;
    int lane = (int)(t & 31);

    int beg = __ldg(rowptr + v);
    int end = __ldg(rowptr + v + 1);

    float ax = 0.f, ay = 0.f, az = 0.f, aw = 0.f;
    int i = beg;
    for (; i + 4 <= end; i += 4) {
        int s0 = __ldg(csr + i + 0);
        int s1 = __ldg(csr + i + 1);
        int s2 = __ldg(csr + i + 2);
        int s3 = __ldg(csr + i + 3);
        float4 f0 = *reinterpret_cast<const float4*>(feat + (size_t)s0 * DIM + lane * 4);
        float4 f1 = *reinterpret_cast<const float4*>(feat + (size_t)s1 * DIM + lane * 4);
        float4 f2 = *reinterpret_cast<const float4*>(feat + (size_t)s2 * DIM + lane * 4);
        float4 f3 = *reinterpret_cast<const float4*>(feat + (size_t)s3 * DIM + lane * 4);
        ax += (f0.x + f1.x) + (f2.x + f3.x);
        ay += (f0.y + f1.y) + (f2.y + f3.y);
        az += (f0.z + f1.z) + (f2.z + f3.z);
        aw += (f0.w + f1.w) + (f2.w + f3.w);
    }
    for (; i < end; ++i) {
        int s0 = __ldg(csr + i);
        float4 f0 = *reinterpret_cast<const float4*>(feat + (size_t)s0 * DIM + lane * 4);
        ax += f0.x; ay += f0.y; az += f0.z; aw += f0.w;
    }
    float sc = __ldg(invdeg + v);
    bf162 h01, l01, h23, l23;
    split2(ax * sc, ay * sc, h01, l01);
    split2(az * sc, aw * sc, h23, l23);
    reinterpret_cast<bf162*>(aggh + (size_t)v * DIM)[lane * 2 + 0] = h01;
    reinterpret_cast<bf162*>(aggh + (size_t)v * DIM)[lane * 2 + 1] = h23;
    reinterpret_cast<bf162*>(aggl + (size_t)v * DIM)[lane * 2 + 0] = l01;
    reinterpret_cast<bf162*>(aggl + (size_t)v * DIM)[lane * 2 + 1] = l23;
}

// ------- layer-3 epilogue: out[v] = S3[v] + invdeg[v] * sum_{s in N(v)} P[s]  (64-wide) -------
__global__ void __launch_bounds__(256)
aggadd_kernel(const float* __restrict__ S, const float* __restrict__ P,
              const int* __restrict__ rowptr, const int* __restrict__ csr,
              const float* __restrict__ invdeg, float* __restrict__ out, int n) {
    long long t = (long long)blockIdx.x * blockDim.x + threadIdx.x;
    int v = (int)(t >> 5);
    if (v >= n) return;
    int lane = (int)(t & 31);
    const int co = lane * 2;   // 2 floats per lane -> 64 cols per warp

    int beg = __ldg(rowptr + v);
    int end = __ldg(rowptr + v + 1);

    float sx = 0.f, sy = 0.f;
    int i = beg;
    for (; i + 4 <= end; i += 4) {
        int s0 = __ldg(csr + i + 0);
        int s1 = __ldg(csr + i + 1);
        int s2 = __ldg(csr + i + 2);
        int s3 = __ldg(csr + i + 3);
        float2 p0 = *reinterpret_cast<const float2*>(P + (size_t)s0 * 64 + co);
        float2 p1 = *reinterpret_cast<const float2*>(P + (size_t)s1 * 64 + co);
        float2 p2 = *reinterpret_cast<const float2*>(P + (size_t)s2 * 64 + co);
        float2 p3 = *reinterpret_cast<const float2*>(P + (size_t)s3 * 64 + co);
        sx += (p0.x + p1.x) + (p2.x + p3.x);
        sy += (p0.y + p1.y) + (p2.y + p3.y);
    }
    for (; i < end; ++i) {
        int s0 = __ldg(csr + i);
        float2 p0 = *reinterpret_cast<const float2*>(P + (size_t)s0 * 64 + co);
        sx += p0.x; sy += p0.y;
    }
    float sc = __ldg(invdeg + v);
    float2 s3v = *reinterpret_cast<const float2*>(S + (size_t)v * 64 + co);
    *reinterpret_cast<float2*>(out + (size_t)v * 64 + co) =
        make_float2(s3v.x + sc * sx, s3v.y + sc * sy);
}

// ---------------- HMMA fused SAGE layer: persistent, cp.async double-buffered ----------------
// smem: [stage0: 4 x 8KB act tiles][stage1] @0/32768; weights @65536 (4 x NOUT*256B).
__device__ __forceinline__ void load_swz(const bf16* __restrict__ g, char* __restrict__ s,
                                         int rows, int t) {
    for (int i = t; i < rows * 16; i += 256) {
        int row = i >> 4, c = i & 15;
        uint4 v = *reinterpret_cast<const uint4*>(g + (size_t)row * 128 + c * 8);
        *reinterpret_cast<uint4*>(s + (size_t)row * 256 + ((c ^ (row & 7)) << 4)) = v;
    }
}
__device__ __forceinline__ void issue_tile(const bf16* __restrict__ xh, const bf16* __restrict__ xl,
                                           const bf16* __restrict__ gh, const bf16* __restrict__ gl,
                                           int row0, int n, uint32_t stage, int t) {
    int valid = min(32, n - row0);
    for (int i = t; i < 512; i += 256) {
        int row = i >> 4, c = i & 15;
        uint32_t off = (uint32_t)row * 256u + (uint32_t)((c ^ (row & 7)) << 4);
        size_t goff = (size_t)(row0 + row) * 128 + c * 8;
        if (row < valid) {
            cp16(stage + off,          xh + goff);
            cp16(stage + 8192u + off,  xl + goff);
            cp16(stage + 16384u + off, gh + goff);
            cp16(stage + 24576u + off, gl + goff);
        } else {
            zero16(stage + off);          zero16(stage + 8192u + off);
            zero16(stage + 16384u + off); zero16(stage + 24576u + off);
        }
    }
}

// h = relu(X@Ws + b + AGG@Wn) -> fp32 h + bf16 hi/lo
template <int NOUT>
__global__ void __launch_bounds__(256, 1)
gemm_kernel(const bf16* __restrict__ xh, const bf16* __restrict__ xl,
            const bf16* __restrict__ gh, const bf16* __restrict__ gl,
            const bf16* __restrict__ wsh, const bf16* __restrict__ wsl,
            const bf16* __restrict__ wnh, const bf16* __restrict__ wnl,
            const float* __restrict__ bias, float* __restrict__ outf,
            bf16* __restrict__ oh, bf16* __restrict__ ol, int n, int ntiles) {
    extern __shared__ char smem[];
    constexpr int NB = NOUT * 256;
    constexpr int WBASE = 65536;
    constexpr int NPW = NOUT / 4;
    constexpr int NT = NPW / 8;
    const uint32_t sb = smem_to_u32(smem);
    const uint32_t wb = sb + WBASE;
    const int t = threadIdx.x, lane = t & 31, wid = t >> 5;

    load_swz(wsh, smem + WBASE,          NOUT, t);
    load_swz(wsl, smem + WBASE + NB,     NOUT, t);
    load_swz(wnh, smem + WBASE + 2 * NB, NOUT, t);
    load_swz(wnl, smem + WBASE + 3 * NB, NOUT, t);

    const int rhalf = (wid & 1) * 16;
    const int n0 = (wid >> 1) * NPW;
    const int arowl = rhalf + (lane & 15);
    const int akh = lane >> 4;
    const int browl = ((lane >> 4) << 3) + (lane & 7);
    const int bkh = (lane >> 3) & 1;

    float breg[NT][2];
#pragma unroll
    for (int nt = 0; nt < NT; ++nt) {
        int c = n0 + nt * 8 + (lane & 3) * 2;
        breg[nt][0] = __ldg(bias + c);
        breg[nt][1] = __ldg(bias + c + 1);
    }

    int tile = blockIdx.x, buf = 0;
    issue_tile(xh, xl, gh, gl, tile * 32, n, sb, t);
    CP_COMMIT();

    for (; tile < ntiles; tile += gridDim.x) {
        const int nxt = tile + gridDim.x;
        if (nxt < ntiles) {
            issue_tile(xh, xl, gh, gl, nxt * 32, n, sb + (uint32_t)(buf ^ 1) * 32768u, t);
            CP_COMMIT();
            CP_WAIT1();
        } else {
            CP_WAIT0();
        }
        __syncthreads();

        const uint32_t ab = sb + (uint32_t)buf * 32768u;
        float acc[NT][4];
#pragma unroll
        for (int q = 0; q < NT; ++q) { acc[q][0] = acc[q][1] = acc[q][2] = acc[q][3] = 0.f; }

#pragma unroll
        for (int ks = 0; ks < 8; ++ks) {
            uint32_t ac = (uint32_t)((2 * ks + akh) ^ (arowl & 7));
            uint32_t aoff = (uint32_t)arowl * 256u + (ac << 4);
            uint32_t Ah[4], Al[4], Gh[4], Gl[4];
            ldsm_x4(Ah, ab + aoff);
            ldsm_x4(Al, ab + 8192u + aoff);
            ldsm_x4(Gh, ab + 16384u + aoff);
            ldsm_x4(Gl, ab + 24576u + aoff);
#pragma unroll
            for (int np = 0; np < NT / 2; ++np) {
                int brow = n0 + np * 16 + browl;
                uint32_t bc = (uint32_t)((2 * ks + bkh) ^ (brow & 7));
                uint32_t boff = (uint32_t)brow * 256u + (bc << 4);
                uint32_t Bsh[4], Bsl[4], Bnh[4], Bnl[4];
                ldsm_x4(Bsh, wb + boff);
                ldsm_x4(Bsl, wb + (uint32_t)NB + boff);
                ldsm_x4(Bnh, wb + (uint32_t)(2 * NB) + boff);
                ldsm_x4(Bnl, wb + (uint32_t)(3 * NB) + boff);
                float* a0 = acc[np * 2];
                float* a1 = acc[np * 2 + 1];
                mma_bf16(a0, Ah, Bsh);  mma_bf16(a1, Ah, Bsh + 2);
                mma_bf16(a0, Gh, Bnh);  mma_bf16(a1, Gh, Bnh + 2);
                mma_bf16(a0, Al, Bsh);  mma_bf16(a1, Al, Bsh + 2);
                mma_bf16(a0, Gl, Bnh);  mma_bf16(a1, Gl, Bnh + 2);
                mma_bf16(a0, Ah, Bsl);  mma_bf16(a1, Ah, Bsl + 2);
                mma_bf16(a0, Gh, Bnl);  mma_bf16(a1, Gh, Bnl + 2);
            }
        }

        const int r0 = tile * 32 + rhalf + (lane >> 2);
        const int r1 = r0 + 8;
#pragma unroll
        for (int nt = 0; nt < NT; ++nt) {
            int c = n0 + nt * 8 + (lane & 3) * 2;
            float v0 = fmaxf(acc[nt][0] + breg[nt][0], 0.f);
            float v1 = fmaxf(acc[nt][1] + breg[nt][1], 0.f);
            float v2 = fmaxf(acc[nt][2] + breg[nt][0], 0.f);
            float v3 = fmaxf(acc[nt][3] + breg[nt][1], 0.f);
            if (r0 < n) {
                *reinterpret_cast<float2*>(outf + (size_t)r0 * NOUT + c) = make_float2(v0, v1);
                bf162 hi, lo;
                split2(v0, v1, hi, lo);
                *reinterpret_cast<bf162*>(oh + (size_t)r0 * NOUT + c) = hi;
                *reinterpret_cast<bf162*>(ol + (size_t)r0 * NOUT + c) = lo;
            }
            if (r1 < n) {
                *reinterpret_cast<float2*>(outf + (size_t)r1 * NOUT + c) = make_float2(v2, v3);
                bf162 hi, lo;
                split2(v2, v3, hi, lo);
                *reinterpret_cast<bf162*>(oh + (size_t)r1 * NOUT + c) = hi;
                *reinterpret_cast<bf162*>(ol + (size_t)r1 * NOUT + c) = lo;
            }
        }
        __syncthreads();
        buf ^= 1;
    }
}

// ---- layer-3 dual GEMM: S = X@Ws + b, P = X@Wn (NOUT=64), A tiles loaded once ----
__device__ __forceinline__ void issue_tile2(const bf16* __restrict__ xh, const bf16* __restrict__ xl,
                                            int row0, int n, uint32_t stage, int t) {
    int valid = min(32, n - row0);
    for (int i = t; i < 512; i += 256) {
        int row = i >> 4, c = i & 15;
        uint32_t off = (uint32_t)row * 256u + (uint32_t)((c ^ (row & 7)) << 4);
        size_t goff = (size_t)(row0 + row) * 128 + c * 8;
        if (row < valid) {
            cp16(stage + off,         xh + goff);
            cp16(stage + 8192u + off, xl + goff);
        } else {
            zero16(stage + off);
            zero16(stage + 8192u + off);
        }
    }
}

__global__ void __launch_bounds__(256, 1)
gemm3_dual_kernel(const bf16* __restrict__ xh, const bf16* __restrict__ xl,
                  const bf16* __restrict__ wsh, const bf16* __restrict__ wsl,
                  const bf16* __restrict__ wnh, const bf16* __restrict__ wnl,
                  const float* __restrict__ bias, float* __restrict__ S,
                  float* __restrict__ P, int n, int ntiles) {
    extern __shared__ char smem[];
    constexpr int NB = 64 * 256;       // 16384 per weight array
    constexpr int WBASE = 32768;       // after 2 x 16KB act stages
    const uint32_t sb = smem_to_u32(smem);
    const uint32_t wb = sb + WBASE;
    const int t = threadIdx.x, lane = t & 31, wid = t >> 5;

    load_swz(wsh, smem + WBASE,          64, t);
    load_swz(wsl, smem + WBASE + NB,     64, t);
    load_swz(wnh, smem + WBASE + 2 * NB, 64, t);
    load_swz(wnl, smem + WBASE + 3 * NB, 64, t);

    const int rhalf = (wid & 1) * 16;
    const int n0 = (wid >> 1) * 16;          // 4 col strips of 16
    const int arowl = rhalf + (lane & 15);
    const int akh = lane >> 4;
    const int browl = ((lane >> 4) << 3) + (lane & 7);
    const int bkh = (lane >> 3) & 1;
    const int brow = n0 + browl;

    float breg[2][2];
#pragma unroll
    for (int nt = 0; nt < 2; ++nt) {
        int c = n0 + nt * 8 + (lane & 3) * 2;
        breg[nt][0] = __ldg(bias + c);
        breg[nt][1] = __ldg(bias + c + 1);
    }

    int tile = blockIdx.x, buf = 0;
    issue_tile2(xh, xl, tile * 32, n, sb, t);
    CP_COMMIT();

    for (; tile < ntiles; tile += gridDim.x) {
        const int nxt = tile + gridDim.x;
        if (nxt < ntiles) {
            issue_tile2(xh, xl, nxt * 32, n, sb + (uint32_t)(buf ^ 1) * 16384u, t);
            CP_COMMIT();
            CP_WAIT1();
        } else {
            CP_WAIT0();
        }
        __syncthreads();

        const uint32_t ab = sb + (uint32_t)buf * 16384u;
        float accS[2][4], accP[2][4];
#pragma unroll
        for (int q = 0; q < 2; ++q) {
            accS[q][0] = accS[q][1] = accS[q][2] = accS[q][3] = 0.f;
            accP[q][0] = accP[q][1] = accP[q][2] = accP[q][3] = 0.f;
        }

#pragma unroll
        for (int ks = 0; ks < 8; ++ks) {
            uint32_t ac = (uint32_t)((2 * ks + akh) ^ (arowl & 7));
            uint32_t aoff = (uint32_t)arowl * 256u + (ac << 4);
            uint32_t Ah[4], Al[4];
            ldsm_x4(Ah, ab + aoff);
            ldsm_x4(Al, ab + 8192u + aoff);
            uint32_t bc = (uint32_t)((2 * ks + bkh) ^ (brow & 7));
            uint32_t boff = (uint32_t)brow * 256u + (bc << 4);
            uint32_t Bsh[4], Bsl[4], Bnh[4], Bnl[4];
            ldsm_x4(Bsh, wb + boff);
            ldsm_x4(Bsl, wb + (uint32_t)NB + boff);
            ldsm_x4(Bnh, wb + (uint32_t)(2 * NB) + boff);
            ldsm_x4(Bnl, wb + (uint32_t)(3 * NB) + boff);
            mma_bf16(accS[0], Ah, Bsh);  mma_bf16(accS[1], Ah, Bsh + 2);
            mma_bf16(accP[0], Ah, Bnh);  mma_bf16(accP[1], Ah, Bnh + 2);
            mma_bf16(accS[0], Al, Bsh);  mma_bf16(accS[1], Al, Bsh + 2);
            mma_bf16(accP[0], Al, Bnh);  mma_bf16(accP[1], Al, Bnh + 2);
            mma_bf16(accS[0], Ah, Bsl);  mma_bf16(accS[1], Ah, Bsl + 2);
            mma_bf16(accP[0], Ah, Bnl);  mma_bf16(accP[1], Ah, Bnl + 2);
        }

        const int r0 = tile * 32 + rhalf + (lane >> 2);
        const int r1 = r0 + 8;
#pragma unroll
        for (int nt = 0; nt < 2; ++nt) {
            int c = n0 + nt * 8 + (lane & 3) * 2;
            if (r0 < n) {
                *reinterpret_cast<float2*>(S + (size_t)r0 * 64 + c) =
                    make_float2(accS[nt][0] + breg[nt][0], accS[nt][1] + breg[nt][1]);
                *reinterpret_cast<float2*>(P + (size_t)r0 * 64 + c) =
                    make_float2(accP[nt][0], accP[nt][1]);
            }
            if (r1 < n) {
                *reinterpret_cast<float2*>(S + (size_t)r1 * 64 + c) =
                    make_float2(accS[nt][2] + breg[nt][0], accS[nt][3] + breg[nt][1]);
                *reinterpret_cast<float2*>(P + (size_t)r1 * 64 + c) =
                    make_float2(accP[nt][2], accP[nt][3]);
            }
        }
        __syncthreads();
        buf ^= 1;
    }
}

// ---------------- launch ----------------
extern "C" void kernel_launch(void* const* d_in, const int* in_sizes, int n_in,
                              void* d_out, int out_size) {
    const float* x   = (const float*)d_in[0];
    const int*   src = (const int*)d_in[1];
    const int*   dst = (const int*)d_in[2];
    const float* Ws1 = (const float*)d_in[3];
    const float* b1  = (const float*)d_in[4];
    const float* Wn1 = (const float*)d_in[5];
    const float* Ws2 = (const float*)d_in[6];
    const float* b2  = (const float*)d_in[7];
    const float* Wn2 = (const float*)d_in[8];
    const float* Ws3 = (const float*)d_in[9];
    const float* b3  = (const float*)d_in[10];
    const float* Wn3 = (const float*)d_in[11];

    const int N = in_sizes[0] / DIM;
    const int E = in_sizes[1];
    float* out = (float*)d_out;

    int *deg_i, *rowptr, *csr;
    float *invdeg, *h, *S3, *P;
    bf16 *xh, *xl, *aggh, *aggl, *hh, *hl, *wth, *wtl;
    cudaGetSymbolAddress((void**)&deg_i,  g_deg_i);
    cudaGetSymbolAddress((void**)&rowptr, g_rowptr);
    cudaGetSymbolAddress((void**)&csr,    g_csr);
    cudaGetSymbolAddress((void**)&invdeg, g_invdeg);
    cudaGetSymbolAddress((void**)&h,      g_h);
    cudaGetSymbolAddress((void**)&S3,     g_S3);
    cudaGetSymbolAddress((void**)&P,      g_P);
    cudaGetSymbolAddress((void**)&xh,     g_xh);
    cudaGetSymbolAddress((void**)&xl,     g_xl);
    cudaGetSymbolAddress((void**)&aggh,   g_aggh);
    cudaGetSymbolAddress((void**)&aggl,   g_aggl);
    cudaGetSymbolAddress((void**)&hh,     g_hh);
    cudaGetSymbolAddress((void**)&hl,     g_hl);
    cudaGetSymbolAddress((void**)&wth,    g_wth);
    cudaGetSymbolAddress((void**)&wtl,    g_wtl);

    // one-time host-side setup (runs on the non-captured correctness call first)
    static cudaStream_t s1 = nullptr;
    static cudaEvent_t evf, ea1;
    if (!s1) {
        cudaStreamCreateWithFlags(&s1, cudaStreamNonBlocking);
        cudaEventCreateWithFlags(&evf, cudaEventDisableTiming);
        cudaEventCreateWithFlags(&ea1, cudaEventDisableTiming);
    }

    const int SM128 = 65536 + 4 * 128 * 256;  // 196608
    const int SM3   = 32768 + 4 * 64 * 256;   // 98304
    cudaFuncSetAttribute(gemm_kernel<128>,
                         cudaFuncAttributeMaxDynamicSharedMemorySize, SM128);
    cudaFuncSetAttribute(gemm3_dual_kernel,
                         cudaFuncAttributeMaxDynamicSharedMemorySize, SM3);

    const int nb_nodes = (N + 255) / 256;
    const int nb_edges = (E + 255) / 256;
    const int nb_agg   = (int)(((long long)N * 32 + 255) / 256);
    const int ntiles   = (N + 31) / 32;
    const int GRID     = 152;

    // ---- fork: s1 builds CSR + agg1 (uses fp32 x) while s0 does the splits ----
    cudaEventRecord(evf, 0);
    cudaStreamWaitEvent(s1, evf, 0);

    zero_int_kernel<<<nb_nodes, 256, 0, s1>>>(deg_i, N);
    deg_kernel<<<nb_edges, 256, 0, s1>>>(dst, deg_i, E);
    scan_kernel<<<1, 1024, 0, s1>>>(deg_i, rowptr, invdeg, N);
    fill_csr_kernel<<<nb_edges, 256, 0, s1>>>(src, dst, rowptr, deg_i, csr, E);
    agg_kernel<<<nb_agg, 256, 0, s1>>>(x, rowptr, csr, invdeg, aggh, aggl, N);
    cudaEventRecord(ea1, s1);

    split_kernel<<<(N * DIM / 2 + 255) / 256, 256>>>(x, xh, xl, N * DIM / 2);
    wsplit_kernel<<<(81920 + 255) / 256, 256>>>(Ws1, Wn1, Ws2, Wn2, Ws3, Wn3, wth, wtl);

    // ---- join; layers run single-stream (persistent GEMMs own the whole chip) ----
    cudaStreamWaitEvent(0, ea1, 0);

    // Layer 1
    gemm_kernel<128><<<GRID, 256, SM128>>>(
        xh, xl, aggh, aggl,
        wth + 0 * 16384, wtl + 0 * 16384, wth + 1 * 16384, wtl + 1 * 16384,
        b1, h, hh, hl, N, ntiles);

    // Layer 2
    agg_kernel<<<nb_agg, 256>>>(h, rowptr, csr, invdeg, aggh, aggl, N);
    gemm_kernel<128><<<GRID, 256, SM128>>>(
        hh, hl, aggh, aggl,
        wth + 2 * 16384, wtl + 2 * 16384, wth + 3 * 16384, wtl + 3 * 16384,
        b2, h, hh, hl, N, ntiles);

    // Layer 3: lin-before-mp (matches reference): S3 = h@Ws3+b3, P = h@Wn3, then mean+add
    gemm3_dual_kernel<<<GRID, 256, SM3>>>(
        hh, hl,
        wth + 4 * 16384, wtl + 4 * 16384, wth + 5 * 16384, wtl + 5 * 16384,
        b3, S3, P, N, ntiles);
    aggadd_kernel<<<nb_agg, 256>>>(S3, P, rowptr, csr, invdeg, out, N);
}

// round 10
// speedup vs baseline: 1.1021x; 1.0091x over previous
#include <cuda_runtime.h>
#include <cuda_bf16.h>
#include <cstdint>

#define DIM 128
#define NODES_MAX 50048
#define EDGES_MAX 800000

typedef __nv_bfloat16 bf16;
typedef __nv_bfloat162 bf162;

// ---------------- device scratch (allocation-free rule) ----------------
__device__ int   g_deg_i[NODES_MAX];
__device__ int   g_rowptr[NODES_MAX + 1];
__device__ int   g_csr[EDGES_MAX];
__device__ float g_invdeg[NODES_MAX];
__device__ __align__(16) float g_h[(size_t)NODES_MAX * DIM];   // fp32 activations (agg input)
__device__ __align__(16) float g_S1[(size_t)NODES_MAX * DIM];  // layer-1 self partial
__device__ __align__(16) float g_S3[(size_t)NODES_MAX * 64];   // layer-3 self partial
__device__ __align__(16) float g_P[(size_t)NODES_MAX * 64];    // layer-3 h@Wn3
__device__ __align__(16) bf16  g_xh[(size_t)NODES_MAX * DIM];  // split-bf16 GEMM inputs
__device__ __align__(16) bf16  g_xl[(size_t)NODES_MAX * DIM];
__device__ __align__(16) bf16  g_aggh[(size_t)NODES_MAX * DIM];
__device__ __align__(16) bf16  g_aggl[(size_t)NODES_MAX * DIM];
__device__ __align__(16) bf16  g_hh[(size_t)NODES_MAX * DIM];
__device__ __align__(16) bf16  g_hl[(size_t)NODES_MAX * DIM];
__device__ __align__(16) bf16  g_wth[6 * 16384];               // transposed [N][K] weight hi
__device__ __align__(16) bf16  g_wtl[6 * 16384];               // lo parts

// ---------------- PTX helpers (sm_80-baseline features only) ----------------
__device__ __forceinline__ uint32_t smem_to_u32(const void* p) {
    uint32_t a;
    asm("{ .reg .u64 t; cvta.to.shared.u64 t, %1; cvt.u32.u64 %0, t; }" : "=r"(a) : "l"(p));
    return a;
}
__device__ __forceinline__ void ldsm_x4(uint32_t* r, uint32_t addr) {
    asm volatile("ldmatrix.sync.aligned.m8n8.x4.shared.b16 {%0,%1,%2,%3}, [%4];"
                 : "=r"(r[0]), "=r"(r[1]), "=r"(r[2]), "=r"(r[3]) : "r"(addr));
}
__device__ __forceinline__ void mma_bf16(float* d, const uint32_t* a, const uint32_t* b) {
    asm volatile(
        "mma.sync.aligned.m16n8k16.row.col.f32.bf16.bf16.f32 "
        "{%0,%1,%2,%3}, {%4,%5,%6,%7}, {%8,%9}, {%0,%1,%2,%3};"
        : "+f"(d[0]), "+f"(d[1]), "+f"(d[2]), "+f"(d[3])
        : "r"(a[0]), "r"(a[1]), "r"(a[2]), "r"(a[3]), "r"(b[0]), "r"(b[1]));
}
__device__ __forceinline__ void cp16(uint32_t d, const void* g) {
    asm volatile("cp.async.cg.shared.global [%0], [%1], 16;" :: "r"(d), "l"(g));
}
__device__ __forceinline__ void zero16(uint32_t d) {
    asm volatile("st.shared.v4.b32 [%0], {%1,%1,%1,%1};" :: "r"(d), "r"(0u));
}
#define CP_COMMIT() asm volatile("cp.async.commit_group;" ::: "memory")
#define CP_WAIT1()  asm volatile("cp.async.wait_group 1;" ::: "memory")
#define CP_WAIT0()  asm volatile("cp.async.wait_group 0;" ::: "memory")

// ---------------- CSR build ----------------
__global__ void zero_int_kernel(int* __restrict__ p, int n) {
    int i = blockIdx.x * blockDim.x + threadIdx.x;
    if (i < n) p[i] = 0;
}
__global__ void deg_kernel(const int* __restrict__ dst, int* __restrict__ deg, int E) {
    int e = blockIdx.x * blockDim.x + threadIdx.x;
    if (e < E) atomicAdd(&deg[dst[e]], 1);
}
__global__ void __launch_bounds__(1024)
scan_kernel(const int* __restrict__ cnt, int* __restrict__ rowptr,
            float* __restrict__ inv, int n) {
    __shared__ int wsum[32];
    const int tid = threadIdx.x;
    const int CH = (n + 1023) / 1024;
    const int base = tid * CH;
    int s = 0;
    for (int j = 0; j < CH; ++j) { int i = base + j; if (i < n) s += __ldg(cnt + i); }
    int v = s;
#pragma unroll
    for (int o = 1; o < 32; o <<= 1) { int u = __shfl_up_sync(~0u, v, o); if ((tid & 31) >= o) v += u; }
    if ((tid & 31) == 31) wsum[tid >> 5] = v;
    __syncthreads();
    if (tid < 32) {
        int w = wsum[tid];
#pragma unroll
        for (int o = 1; o < 32; o <<= 1) { int u = __shfl_up_sync(~0u, w, o); if (tid >= o) w += u; }
        wsum[tid] = w;
    }
    __syncthreads();
    int run = (v - s) + ((tid >= 32) ? wsum[(tid >> 5) - 1] : 0);
    for (int j = 0; j < CH; ++j) {
        int i = base + j;
        if (i < n) {
            int c = __ldg(cnt + i);
            run += c;
            rowptr[i + 1] = run;
            inv[i] = 1.0f / (float)max(c, 1);
        }
    }
    if (tid == 0) rowptr[0] = 0;
}
__global__ void fill_csr_kernel(const int* __restrict__ src, const int* __restrict__ dst,
                                const int* __restrict__ rowptr, int* __restrict__ deg,
                                int* __restrict__ csr, int E) {
    int e = blockIdx.x * blockDim.x + threadIdx.x;
    if (e < E) {
        int d = dst[e];
        int cnt = atomicAdd(&deg[d], -1);
        csr[rowptr[d] + cnt - 1] = src[e];
    }
}

// ---------------- split conversions ----------------
__device__ __forceinline__ void split2(float v0, float v1, bf162& hi, bf162& lo) {
    bf16 h0 = __float2bfloat16(v0), h1 = __float2bfloat16(v1);
    bf16 l0 = __float2bfloat16(v0 - __bfloat162float(h0));
    bf16 l1 = __float2bfloat16(v1 - __bfloat162float(h1));
    hi = __halves2bfloat162(h0, h1);
    lo = __halves2bfloat162(l0, l1);
}
__global__ void split_kernel(const float* __restrict__ x, bf16* __restrict__ h,
                             bf16* __restrict__ l, int n2) {
    int i = blockIdx.x * blockDim.x + threadIdx.x;
    if (i < n2) {
        float2 v = reinterpret_cast<const float2*>(x)[i];
        bf162 hi, lo;
        split2(v.x, v.y, hi, lo);
        reinterpret_cast<bf162*>(h)[i] = hi;
        reinterpret_cast<bf162*>(l)[i] = lo;
    }
}
__global__ void wsplit_kernel(const float* W1s, const float* W1n, const float* W2s,
                              const float* W2n, const float* W3s, const float* W3n,
                              bf16* __restrict__ th, bf16* __restrict__ tl) {
    int i = blockIdx.x * blockDim.x + threadIdx.x;
    int m, off;
    if (i < 4 * 16384) { m = i / 16384; off = i % 16384; }
    else {
        int j = i - 4 * 16384;
        if (j >= 2 * 8192) return;
        m = 4 + j / 8192; off = j % 8192;
    }
    const float* src = (m == 0) ? W1s : (m == 1) ? W1n : (m == 2) ? W2s
                     : (m == 3) ? W2n : (m == 4) ? W3s : W3n;
    int Ncols = (m < 4) ? 128 : 64;
    int nn = off / 128, kk = off % 128;
    float v = src[kk * Ncols + nn];
    bf16 h = __float2bfloat16(v);
    th[m * 16384 + off] = h;
    tl[m * 16384 + off] = __float2bfloat16(v - __bfloat162float(h));
}

// ---------------- atomic-free mean aggregation (fp32 gather -> split bf16 out) ----------------
__global__ void __launch_bounds__(256)
agg_kernel(const float* __restrict__ feat, const int* __restrict__ rowptr,
           const int* __restrict__ csr, const float* __restrict__ invdeg,
           bf16* __restrict__ aggh, bf16* __restrict__ aggl, int n) {
    long long t = (long long)blockIdx.x * blockDim.x + threadIdx.x;
    int v = (int)(t >> 5);
    if (v >= n) return;
    int lane = (int)(t & 31);

    int beg = __ldg(rowptr + v);
    int end = __ldg(rowptr + v + 1);

    float ax = 0.f, ay = 0.f, az = 0.f, aw = 0.f;
    int i = beg;
    for (; i + 4 <= end; i += 4) {
        int s0 = __ldg(csr + i + 0);
        int s1 = __ldg(csr + i + 1);
        int s2 = __ldg(csr + i + 2);
        int s3 = __ldg(csr + i + 3);
        float4 f0 = *reinterpret_cast<const float4*>(feat + (size_t)s0 * DIM + lane * 4);
        float4 f1 = *reinterpret_cast<const float4*>(feat + (size_t)s1 * DIM + lane * 4);
        float4 f2 = *reinterpret_cast<const float4*>(feat + (size_t)s2 * DIM + lane * 4);
        float4 f3 = *reinterpret_cast<const float4*>(feat + (size_t)s3 * DIM + lane * 4);
        ax += (f0.x + f1.x) + (f2.x + f3.x);
        ay += (f0.y + f1.y) + (f2.y + f3.y);
        az += (f0.z + f1.z) + (f2.z + f3.z);
        aw += (f0.w + f1.w) + (f2.w + f3.w);
    }
    for (; i < end; ++i) {
        int s0 = __ldg(csr + i);
        float4 f0 = *reinterpret_cast<const float4*>(feat + (size_t)s0 * DIM + lane * 4);
        ax += f0.x; ay += f0.y; az += f0.z; aw += f0.w;
    }
    float sc = __ldg(invdeg + v);
    bf162 h01, l01, h23, l23;
    split2(ax * sc, ay * sc, h01, l01);
    split2(az * sc, aw * sc, h23, l23);
    reinterpret_cast<bf162*>(aggh + (size_t)v * DIM)[lane * 2 + 0] = h01;
    reinterpret_cast<bf162*>(aggh + (size_t)v * DIM)[lane * 2 + 1] = h23;
    reinterpret_cast<bf162*>(aggl + (size_t)v * DIM)[lane * 2 + 0] = l01;
    reinterpret_cast<bf162*>(aggl + (size_t)v * DIM)[lane * 2 + 1] = l23;
}

// ------- layer-3 epilogue: out[v] = S3[v] + invdeg[v] * sum_{s in N(v)} P[s]  (64-wide) -------
__global__ void __launch_bounds__(256)
aggadd_kernel(const float* __restrict__ S, const float* __restrict__ P,
              const int* __restrict__ rowptr, const int* __restrict__ csr,
              const float* __restrict__ invdeg, float* __restrict__ out, int n) {
    long long t = (long long)blockIdx.x * blockDim.x + threadIdx.x;
    int v = (int)(t >> 5);
    if (v >= n) return;
    int lane = (int)(t & 31);
    const int co = lane * 2;

    int beg = __ldg(rowptr + v);
    int end = __ldg(rowptr + v + 1);

    float sx = 0.f, sy = 0.f;
    int i = beg;
    for (; i + 4 <= end; i += 4) {
        int s0 = __ldg(csr + i + 0);
        int s1 = __ldg(csr + i + 1);
        int s2 = __ldg(csr + i + 2);
        int s3 = __ldg(csr + i + 3);
        float2 p0 = *reinterpret_cast<const float2*>(P + (size_t)s0 * 64 + co);
        float2 p1 = *reinterpret_cast<const float2*>(P + (size_t)s1 * 64 + co);
        float2 p2 = *reinterpret_cast<const float2*>(P + (size_t)s2 * 64 + co);
        float2 p3 = *reinterpret_cast<const float2*>(P + (size_t)s3 * 64 + co);
        sx += (p0.x + p1.x) + (p2.x + p3.x);
        sy += (p0.y + p1.y) + (p2.y + p3.y);
    }
    for (; i < end; ++i) {
        int s0 = __ldg(csr + i);
        float2 p0 = *reinterpret_cast<const float2*>(P + (size_t)s0 * 64 + co);
        sx += p0.x; sy += p0.y;
    }
    float sc = __ldg(invdeg + v);
    float2 s3v = *reinterpret_cast<const float2*>(S + (size_t)v * 64 + co);
    *reinterpret_cast<float2*>(out + (size_t)v * 64 + co) =
        make_float2(s3v.x + sc * sx, s3v.y + sc * sy);
}

// ---------------- shared GEMM building blocks ----------------
__device__ __forceinline__ void load_swz(const bf16* __restrict__ g, char* __restrict__ s,
                                         int rows, int t) {
    for (int i = t; i < rows * 16; i += 256) {
        int row = i >> 4, c = i & 15;
        uint4 v = *reinterpret_cast<const uint4*>(g + (size_t)row * 128 + c * 8);
        *reinterpret_cast<uint4*>(s + (size_t)row * 256 + ((c ^ (row & 7)) << 4)) = v;
    }
}
__device__ __forceinline__ void issue_tile4(const bf16* __restrict__ xh, const bf16* __restrict__ xl,
                                            const bf16* __restrict__ gh, const bf16* __restrict__ gl,
                                            int row0, int n, uint32_t stage, int t) {
    int valid = min(32, n - row0);
    for (int i = t; i < 512; i += 256) {
        int row = i >> 4, c = i & 15;
        uint32_t off = (uint32_t)row * 256u + (uint32_t)((c ^ (row & 7)) << 4);
        size_t goff = (size_t)(row0 + row) * 128 + c * 8;
        if (row < valid) {
            cp16(stage + off,          xh + goff);
            cp16(stage + 8192u + off,  xl + goff);
            cp16(stage + 16384u + off, gh + goff);
            cp16(stage + 24576u + off, gl + goff);
        } else {
            zero16(stage + off);          zero16(stage + 8192u + off);
            zero16(stage + 16384u + off); zero16(stage + 24576u + off);
        }
    }
}
__device__ __forceinline__ void issue_tile2(const bf16* __restrict__ xh, const bf16* __restrict__ xl,
                                            int row0, int n, uint32_t stage, int t) {
    int valid = min(32, n - row0);
    for (int i = t; i < 512; i += 256) {
        int row = i >> 4, c = i & 15;
        uint32_t off = (uint32_t)row * 256u + (uint32_t)((c ^ (row & 7)) << 4);
        size_t goff = (size_t)(row0 + row) * 128 + c * 8;
        if (row < valid) {
            cp16(stage + off,         xh + goff);
            cp16(stage + 8192u + off, xl + goff);
        } else {
            zero16(stage + off);
            zero16(stage + 8192u + off);
        }
    }
}

// ---- fused full layer (layer 2): h = relu(X@Ws + b + AGG@Wn) -> fp32 h + bf16 hi/lo ----
template <int NOUT>
__global__ void __launch_bounds__(256, 1)
gemm_kernel(const bf16* __restrict__ xh, const bf16* __restrict__ xl,
            const bf16* __restrict__ gh, const bf16* __restrict__ gl,
            const bf16* __restrict__ wsh, const bf16* __restrict__ wsl,
            const bf16* __restrict__ wnh, const bf16* __restrict__ wnl,
            const float* __restrict__ bias, float* __restrict__ outf,
            bf16* __restrict__ oh, bf16* __restrict__ ol, int n, int ntiles) {
    extern __shared__ char smem[];
    constexpr int NB = NOUT * 256;
    constexpr int WBASE = 65536;
    constexpr int NPW = NOUT / 4;
    constexpr int NT = NPW / 8;
    const uint32_t sb = smem_to_u32(smem);
    const uint32_t wb = sb + WBASE;
    const int t = threadIdx.x, lane = t & 31, wid = t >> 5;

    load_swz(wsh, smem + WBASE,          NOUT, t);
    load_swz(wsl, smem + WBASE + NB,     NOUT, t);
    load_swz(wnh, smem + WBASE + 2 * NB, NOUT, t);
    load_swz(wnl, smem + WBASE + 3 * NB, NOUT, t);

    const int rhalf = (wid & 1) * 16;
    const int n0 = (wid >> 1) * NPW;
    const int arowl = rhalf + (lane & 15);
    const int akh = lane >> 4;
    const int browl = ((lane >> 4) << 3) + (lane & 7);
    const int bkh = (lane >> 3) & 1;

    float breg[NT][2];
#pragma unroll
    for (int nt = 0; nt < NT; ++nt) {
        int c = n0 + nt * 8 + (lane & 3) * 2;
        breg[nt][0] = __ldg(bias + c);
        breg[nt][1] = __ldg(bias + c + 1);
    }

    int tile = blockIdx.x, buf = 0;
    issue_tile4(xh, xl, gh, gl, tile * 32, n, sb, t);
    CP_COMMIT();

    for (; tile < ntiles; tile += gridDim.x) {
        const int nxt = tile + gridDim.x;
        if (nxt < ntiles) {
            issue_tile4(xh, xl, gh, gl, nxt * 32, n, sb + (uint32_t)(buf ^ 1) * 32768u, t);
            CP_COMMIT();
            CP_WAIT1();
        } else {
            CP_WAIT0();
        }
        __syncthreads();

        const uint32_t ab = sb + (uint32_t)buf * 32768u;
        float acc[NT][4];
#pragma unroll
        for (int q = 0; q < NT; ++q) { acc[q][0] = acc[q][1] = acc[q][2] = acc[q][3] = 0.f; }

#pragma unroll
        for (int ks = 0; ks < 8; ++ks) {
            uint32_t ac = (uint32_t)((2 * ks + akh) ^ (arowl & 7));
            uint32_t aoff = (uint32_t)arowl * 256u + (ac << 4);
            uint32_t Ah[4], Al[4], Gh[4], Gl[4];
            ldsm_x4(Ah, ab + aoff);
            ldsm_x4(Al, ab + 8192u + aoff);
            ldsm_x4(Gh, ab + 16384u + aoff);
            ldsm_x4(Gl, ab + 24576u + aoff);
#pragma unroll
            for (int np = 0; np < NT / 2; ++np) {
                int brow = n0 + np * 16 + browl;
                uint32_t bc = (uint32_t)((2 * ks + bkh) ^ (brow & 7));
                uint32_t boff = (uint32_t)brow * 256u + (bc << 4);
                uint32_t Bsh[4], Bsl[4], Bnh[4], Bnl[4];
                ldsm_x4(Bsh, wb + boff);
                ldsm_x4(Bsl, wb + (uint32_t)NB + boff);
                ldsm_x4(Bnh, wb + (uint32_t)(2 * NB) + boff);
                ldsm_x4(Bnl, wb + (uint32_t)(3 * NB) + boff);
                float* a0 = acc[np * 2];
                float* a1 = acc[np * 2 + 1];
                mma_bf16(a0, Ah, Bsh);  mma_bf16(a1, Ah, Bsh + 2);
                mma_bf16(a0, Gh, Bnh);  mma_bf16(a1, Gh, Bnh + 2);
                mma_bf16(a0, Al, Bsh);  mma_bf16(a1, Al, Bsh + 2);
                mma_bf16(a0, Gl, Bnh);  mma_bf16(a1, Gl, Bnh + 2);
                mma_bf16(a0, Ah, Bsl);  mma_bf16(a1, Ah, Bsl + 2);
                mma_bf16(a0, Gh, Bnl);  mma_bf16(a1, Gh, Bnl + 2);
            }
        }

        const int r0 = tile * 32 + rhalf + (lane >> 2);
        const int r1 = r0 + 8;
#pragma unroll
        for (int nt = 0; nt < NT; ++nt) {
            int c = n0 + nt * 8 + (lane & 3) * 2;
            float v0 = fmaxf(acc[nt][0] + breg[nt][0], 0.f);
            float v1 = fmaxf(acc[nt][1] + breg[nt][1], 0.f);
            float v2 = fmaxf(acc[nt][2] + breg[nt][0], 0.f);
            float v3 = fmaxf(acc[nt][3] + breg[nt][1], 0.f);
            if (r0 < n) {
                *reinterpret_cast<float2*>(outf + (size_t)r0 * NOUT + c) = make_float2(v0, v1);
                bf162 hi, lo;
                split2(v0, v1, hi, lo);
                *reinterpret_cast<bf162*>(oh + (size_t)r0 * NOUT + c) = hi;
                *reinterpret_cast<bf162*>(ol + (size_t)r0 * NOUT + c) = lo;
            }
            if (r1 < n) {
                *reinterpret_cast<float2*>(outf + (size_t)r1 * NOUT + c) = make_float2(v2, v3);
                bf162 hi, lo;
                split2(v2, v3, hi, lo);
                *reinterpret_cast<bf162*>(oh + (size_t)r1 * NOUT + c) = hi;
                *reinterpret_cast<bf162*>(ol + (size_t)r1 * NOUT + c) = lo;
            }
        }
        __syncthreads();
        buf ^= 1;
    }
}

// ---- half-layer GEMM (layer 1 split). MODE 0: S = A@W + b. MODE 1: h = relu(S + A@W),
//      writes fp32 h + bf16 hi/lo. smem: 2 x 16KB act stages + 2 weight arrays. ----
template <int NOUT, int MODE>
__global__ void __launch_bounds__(256, 1)
gemm_half_kernel(const bf16* __restrict__ ah, const bf16* __restrict__ al,
                 const bf16* __restrict__ wh, const bf16* __restrict__ wl,
                 const float* __restrict__ aux, float* __restrict__ outf,
                 bf16* __restrict__ oh, bf16* __restrict__ ol, int n, int ntiles) {
    extern __shared__ char smem[];
    constexpr int NB = NOUT * 256;
    constexpr int WBASE = 32768;
    constexpr int NPW = NOUT / 4;
    constexpr int NT = NPW / 8;
    const uint32_t sb = smem_to_u32(smem);
    const uint32_t wb = sb + WBASE;
    const int t = threadIdx.x, lane = t & 31, wid = t >> 5;

    load_swz(wh, smem + WBASE,      NOUT, t);
    load_swz(wl, smem + WBASE + NB, NOUT, t);

    const int rhalf = (wid & 1) * 16;
    const int n0 = (wid >> 1) * NPW;
    const int arowl = rhalf + (lane & 15);
    const int akh = lane >> 4;
    const int browl = ((lane >> 4) << 3) + (lane & 7);
    const int bkh = (lane >> 3) & 1;

    float breg[NT][2];
    if (MODE == 0) {
#pragma unroll
        for (int nt = 0; nt < NT; ++nt) {
            int c = n0 + nt * 8 + (lane & 3) * 2;
            breg[nt][0] = __ldg(aux + c);
            breg[nt][1] = __ldg(aux + c + 1);
        }
    }

    int tile = blockIdx.x, buf = 0;
    issue_tile2(ah, al, tile * 32, n, sb, t);
    CP_COMMIT();

    for (; tile < ntiles; tile += gridDim.x) {
        const int nxt = tile + gridDim.x;
        if (nxt < ntiles) {
            issue_tile2(ah, al, nxt * 32, n, sb + (uint32_t)(buf ^ 1) * 16384u, t);
            CP_COMMIT();
            CP_WAIT1();
        } else {
            CP_WAIT0();
        }
        __syncthreads();

        const uint32_t ab = sb + (uint32_t)buf * 16384u;
        float acc[NT][4];
#pragma unroll
        for (int q = 0; q < NT; ++q) { acc[q][0] = acc[q][1] = acc[q][2] = acc[q][3] = 0.f; }

#pragma unroll
        for (int ks = 0; ks < 8; ++ks) {
            uint32_t ac = (uint32_t)((2 * ks + akh) ^ (arowl & 7));
            uint32_t aoff = (uint32_t)arowl * 256u + (ac << 4);
            uint32_t Ah[4], Al[4];
            ldsm_x4(Ah, ab + aoff);
            ldsm_x4(Al, ab + 8192u + aoff);
#pragma unroll
            for (int np = 0; np < NT / 2; ++np) {
                int brow = n0 + np * 16 + browl;
                uint32_t bc = (uint32_t)((2 * ks + bkh) ^ (brow & 7));
                uint32_t boff = (uint32_t)brow * 256u + (bc << 4);
                uint32_t Bh[4], Bl[4];
                ldsm_x4(Bh, wb + boff);
                ldsm_x4(Bl, wb + (uint32_t)NB + boff);
                float* a0 = acc[np * 2];
                float* a1 = acc[np * 2 + 1];
                mma_bf16(a0, Ah, Bh);  mma_bf16(a1, Ah, Bh + 2);
                mma_bf16(a0, Al, Bh);  mma_bf16(a1, Al, Bh + 2);
                mma_bf16(a0, Ah, Bl);  mma_bf16(a1, Ah, Bl + 2);
            }
        }

        const int r0 = tile * 32 + rhalf + (lane >> 2);
        const int r1 = r0 + 8;
#pragma unroll
        for (int nt = 0; nt < NT; ++nt) {
            int c = n0 + nt * 8 + (lane & 3) * 2;
            float v0 = acc[nt][0], v1 = acc[nt][1], v2 = acc[nt][2], v3 = acc[nt][3];
            if (MODE == 0) {
                v0 += breg[nt][0]; v1 += breg[nt][1];
                v2 += breg[nt][0]; v3 += breg[nt][1];
                if (r0 < n)
                    *reinterpret_cast<float2*>(outf + (size_t)r0 * NOUT + c) = make_float2(v0, v1);
                if (r1 < n)
                    *reinterpret_cast<float2*>(outf + (size_t)r1 * NOUT + c) = make_float2(v2, v3);
            } else {
                if (r0 < n) {
                    float2 s = *reinterpret_cast<const float2*>(aux + (size_t)r0 * NOUT + c);
                    v0 = fmaxf(v0 + s.x, 0.f); v1 = fmaxf(v1 + s.y, 0.f);
                    *reinterpret_cast<float2*>(outf + (size_t)r0 * NOUT + c) = make_float2(v0, v1);
                    bf162 hi, lo;
                    split2(v0, v1, hi, lo);
                    *reinterpret_cast<bf162*>(oh + (size_t)r0 * NOUT + c) = hi;
                    *reinterpret_cast<bf162*>(ol + (size_t)r0 * NOUT + c) = lo;
                }
                if (r1 < n) {
                    float2 s = *reinterpret_cast<const float2*>(aux + (size_t)r1 * NOUT + c);
                    v2 = fmaxf(v2 + s.x, 0.f); v3 = fmaxf(v3 + s.y, 0.f);
                    *reinterpret_cast<float2*>(outf + (size_t)r1 * NOUT + c) = make_float2(v2, v3);
                    bf162 hi, lo;
                    split2(v2, v3, hi, lo);
                    *reinterpret_cast<bf162*>(oh + (size_t)r1 * NOUT + c) = hi;
                    *reinterpret_cast<bf162*>(ol + (size_t)r1 * NOUT + c) = lo;
                }
            }
        }
        __syncthreads();
        buf ^= 1;
    }
}

// ---- layer-3 dual GEMM: S = X@Ws + b, P = X@Wn (NOUT=64), A tiles loaded once ----
__global__ void __launch_bounds__(256, 1)
gemm3_dual_kernel(const bf16* __restrict__ xh, const bf16* __restrict__ xl,
                  const bf16* __restrict__ wsh, const bf16* __restrict__ wsl,
                  const bf16* __restrict__ wnh, const bf16* __restrict__ wnl,
                  const float* __restrict__ bias, float* __restrict__ S,
                  float* __restrict__ P, int n, int ntiles) {
    extern __shared__ char smem[];
    constexpr int NB = 64 * 256;
    constexpr int WBASE = 32768;
    const uint32_t sb = smem_to_u32(smem);
    const uint32_t wb = sb + WBASE;
    const int t = threadIdx.x, lane = t & 31, wid = t >> 5;

    load_swz(wsh, smem + WBASE,          64, t);
    load_swz(wsl, smem + WBASE + NB,     64, t);
    load_swz(wnh, smem + WBASE + 2 * NB, 64, t);
    load_swz(wnl, smem + WBASE + 3 * NB, 64, t);

    const int rhalf = (wid & 1) * 16;
    const int n0 = (wid >> 1) * 16;
    const int arowl = rhalf + (lane & 15);
    const int akh = lane >> 4;
    const int browl = ((lane >> 4) << 3) + (lane & 7);
    const int bkh = (lane >> 3) & 1;
    const int brow = n0 + browl;

    float breg[2][2];
#pragma unroll
    for (int nt = 0; nt < 2; ++nt) {
        int c = n0 + nt * 8 + (lane & 3) * 2;
        breg[nt][0] = __ldg(bias + c);
        breg[nt][1] = __ldg(bias + c + 1);
    }

    int tile = blockIdx.x, buf = 0;
    issue_tile2(xh, xl, tile * 32, n, sb, t);
    CP_COMMIT();

    for (; tile < ntiles; tile += gridDim.x) {
        const int nxt = tile + gridDim.x;
        if (nxt < ntiles) {
            issue_tile2(xh, xl, nxt * 32, n, sb + (uint32_t)(buf ^ 1) * 16384u, t);
            CP_COMMIT();
            CP_WAIT1();
        } else {
            CP_WAIT0();
        }
        __syncthreads();

        const uint32_t ab = sb + (uint32_t)buf * 16384u;
        float accS[2][4], accP[2][4];
#pragma unroll
        for (int q = 0; q < 2; ++q) {
            accS[q][0] = accS[q][1] = accS[q][2] = accS[q][3] = 0.f;
            accP[q][0] = accP[q][1] = accP[q][2] = accP[q][3] = 0.f;
        }

#pragma unroll
        for (int ks = 0; ks < 8; ++ks) {
            uint32_t ac = (uint32_t)((2 * ks + akh) ^ (arowl & 7));
            uint32_t aoff = (uint32_t)arowl * 256u + (ac << 4);
            uint32_t Ah[4], Al[4];
            ldsm_x4(Ah, ab + aoff);
            ldsm_x4(Al, ab + 8192u + aoff);
            uint32_t bc = (uint32_t)((2 * ks + bkh) ^ (brow & 7));
            uint32_t boff = (uint32_t)brow * 256u + (bc << 4);
            uint32_t Bsh[4], Bsl[4], Bnh[4], Bnl[4];
            ldsm_x4(Bsh, wb + boff);
            ldsm_x4(Bsl, wb + (uint32_t)NB + boff);
            ldsm_x4(Bnh, wb + (uint32_t)(2 * NB) + boff);
            ldsm_x4(Bnl, wb + (uint32_t)(3 * NB) + boff);
            mma_bf16(accS[0], Ah, Bsh);  mma_bf16(accS[1], Ah, Bsh + 2);
            mma_bf16(accP[0], Ah, Bnh);  mma_bf16(accP[1], Ah, Bnh + 2);
            mma_bf16(accS[0], Al, Bsh);  mma_bf16(accS[1], Al, Bsh + 2);
            mma_bf16(accP[0], Al, Bnh);  mma_bf16(accP[1], Al, Bnh + 2);
            mma_bf16(accS[0], Ah, Bsl);  mma_bf16(accS[1], Ah, Bsl + 2);
            mma_bf16(accP[0], Ah, Bnl);  mma_bf16(accP[1], Ah, Bnl + 2);
        }

        const int r0 = tile * 32 + rhalf + (lane >> 2);
        const int r1 = r0 + 8;
#pragma unroll
        for (int nt = 0; nt < 2; ++nt) {
            int c = n0 + nt * 8 + (lane & 3) * 2;
            if (r0 < n) {
                *reinterpret_cast<float2*>(S + (size_t)r0 * 64 + c) =
                    make_float2(accS[nt][0] + breg[nt][0], accS[nt][1] + breg[nt][1]);
                *reinterpret_cast<float2*>(P + (size_t)r0 * 64 + c) =
                    make_float2(accP[nt][0], accP[nt][1]);
            }
            if (r1 < n) {
                *reinterpret_cast<float2*>(S + (size_t)r1 * 64 + c) =
                    make_float2(accS[nt][2] + breg[nt][0], accS[nt][3] + breg[nt][1]);
                *reinterpret_cast<float2*>(P + (size_t)r1 * 64 + c) =
                    make_float2(accP[nt][2], accP[nt][3]);
            }
        }
        __syncthreads();
        buf ^= 1;
    }
}

// ---------------- launch ----------------
extern "C" void kernel_launch(void* const* d_in, const int* in_sizes, int n_in,
                              void* d_out, int out_size) {
    const float* x   = (const float*)d_in[0];
    const int*   src = (const int*)d_in[1];
    const int*   dst = (const int*)d_in[2];
    const float* Ws1 = (const float*)d_in[3];
    const float* b1  = (const float*)d_in[4];
    const float* Wn1 = (const float*)d_in[5];
    const float* Ws2 = (const float*)d_in[6];
    const float* b2  = (const float*)d_in[7];
    const float* Wn2 = (const float*)d_in[8];
    const float* Ws3 = (const float*)d_in[9];
    const float* b3  = (const float*)d_in[10];
    const float* Wn3 = (const float*)d_in[11];

    const int N = in_sizes[0] / DIM;
    const int E = in_sizes[1];
    float* out = (float*)d_out;

    int *deg_i, *rowptr, *csr;
    float *invdeg, *h, *S1, *S3, *P;
    bf16 *xh, *xl, *aggh, *aggl, *hh, *hl, *wth, *wtl;
    cudaGetSymbolAddress((void**)&deg_i,  g_deg_i);
    cudaGetSymbolAddress((void**)&rowptr, g_rowptr);
    cudaGetSymbolAddress((void**)&csr,    g_csr);
    cudaGetSymbolAddress((void**)&invdeg, g_invdeg);
    cudaGetSymbolAddress((void**)&h,      g_h);
    cudaGetSymbolAddress((void**)&S1,     g_S1);
    cudaGetSymbolAddress((void**)&S3,     g_S3);
    cudaGetSymbolAddress((void**)&P,      g_P);
    cudaGetSymbolAddress((void**)&xh,     g_xh);
    cudaGetSymbolAddress((void**)&xl,     g_xl);
    cudaGetSymbolAddress((void**)&aggh,   g_aggh);
    cudaGetSymbolAddress((void**)&aggl,   g_aggl);
    cudaGetSymbolAddress((void**)&hh,     g_hh);
    cudaGetSymbolAddress((void**)&hl,     g_hl);
    cudaGetSymbolAddress((void**)&wth,    g_wth);
    cudaGetSymbolAddress((void**)&wtl,    g_wtl);

    // one-time host-side setup (runs on the non-captured correctness call first)
    static cudaStream_t s1 = nullptr;
    static cudaEvent_t evf, ea1;
    if (!s1) {
        cudaStreamCreateWithFlags(&s1, cudaStreamNonBlocking);
        cudaEventCreateWithFlags(&evf, cudaEventDisableTiming);
        cudaEventCreateWithFlags(&ea1, cudaEventDisableTiming);
    }

    const int SM128 = 65536 + 4 * 128 * 256;  // 196608 (fused layer 2)
    const int SMH   = 32768 + 2 * 128 * 256;  // 98304  (half GEMMs, layer 1)
    const int SM3   = 32768 + 4 * 64 * 256;   // 98304  (layer-3 dual)
    cudaFuncSetAttribute(gemm_kernel<128>,
                         cudaFuncAttributeMaxDynamicSharedMemorySize, SM128);
    cudaFuncSetAttribute(gemm_half_kernel<128, 0>,
                         cudaFuncAttributeMaxDynamicSharedMemorySize, SMH);
    cudaFuncSetAttribute(gemm_half_kernel<128, 1>,
                         cudaFuncAttributeMaxDynamicSharedMemorySize, SMH);
    cudaFuncSetAttribute(gemm3_dual_kernel,
                         cudaFuncAttributeMaxDynamicSharedMemorySize, SM3);

    const int nb_nodes = (N + 255) / 256;
    const int nb_edges = (E + 255) / 256;
    const int nb_agg   = (int)(((long long)N * 32 + 255) / 256);
    const int ntiles   = (N + 31) / 32;
    const int GRID     = 152;

    // ---- fork: s1 builds CSR + agg1 while s0 does splits + self-GEMM-1 ----
    cudaEventRecord(evf, 0);
    cudaStreamWaitEvent(s1, evf, 0);

    zero_int_kernel<<<nb_nodes, 256, 0, s1>>>(deg_i, N);
    deg_kernel<<<nb_edges, 256, 0, s1>>>(dst, deg_i, E);
    scan_kernel<<<1, 1024, 0, s1>>>(deg_i, rowptr, invdeg, N);
    fill_csr_kernel<<<nb_edges, 256, 0, s1>>>(src, dst, rowptr, deg_i, csr, E);
    agg_kernel<<<nb_agg, 256, 0, s1>>>(x, rowptr, csr, invdeg, aggh, aggl, N);
    cudaEventRecord(ea1, s1);

    split_kernel<<<(N * DIM / 2 + 255) / 256, 256>>>(x, xh, xl, N * DIM / 2);
    wsplit_kernel<<<(81920 + 255) / 256, 256>>>(Ws1, Wn1, Ws2, Wn2, Ws3, Wn3, wth, wtl);
    gemm_half_kernel<128, 0><<<GRID, 256, SMH>>>(
        xh, xl, wth + 0 * 16384, wtl + 0 * 16384, b1, S1, nullptr, nullptr, N, ntiles);

    // ---- join: layer-1 neigh + the rest run single-stream ----
    cudaStreamWaitEvent(0, ea1, 0);
    gemm_half_kernel<128, 1><<<GRID, 256, SMH>>>(
        aggh, aggl, wth + 1 * 16384, wtl + 1 * 16384, S1, h, hh, hl, N, ntiles);

    // Layer 2 (fused)
    agg_kernel<<<nb_agg, 256>>>(h, rowptr, csr, invdeg, aggh, aggl, N);
    gemm_kernel<128><<<GRID, 256, SM128>>>(
        hh, hl, aggh, aggl,
        wth + 2 * 16384, wtl + 2 * 16384, wth + 3 * 16384, wtl + 3 * 16384,
        b2, h, hh, hl, N, ntiles);

    // Layer 3: lin-before-mp (matches reference)
    gemm3_dual_kernel<<<GRID, 256, SM3>>>(
        hh, hl,
        wth + 4 * 16384, wtl + 4 * 16384, wth + 5 * 16384, wtl + 5 * 16384,
        b3, S3, P, N, ntiles);
    aggadd_kernel<<<nb_agg, 256>>>(S3, P, rowptr, csr, invdeg, out, N);
}

// round 11
// speedup vs baseline: 1.1549x; 1.0479x over previous
#include <cuda_runtime.h>
#include <cuda_bf16.h>
#include <cuda_fp16.h>
#include <cstdint>

#define DIM 128
#define NODES_MAX 50048
#define EDGES_MAX 800000

typedef __nv_bfloat16 bf16;
typedef __nv_bfloat162 bf162;

// ---------------- device scratch (allocation-free rule) ----------------
__device__ int   g_deg_i[NODES_MAX];
__device__ int   g_rowptr[NODES_MAX + 1];
__device__ int   g_csr[EDGES_MAX];
__device__ float g_invdeg[NODES_MAX];
__device__ __align__(16) float  g_S1[(size_t)NODES_MAX * DIM];  // layer-1 self partial
__device__ __align__(16) float  g_S3[(size_t)NODES_MAX * 64];   // layer-3 self partial
__device__ __align__(16) __half g_P16[(size_t)NODES_MAX * 64];  // layer-3 h@Wn3 (fp16)
__device__ __align__(16) __half g_xf16[(size_t)NODES_MAX * DIM];// fp16 activations (agg input)
__device__ __align__(16) __half g_hf16[(size_t)NODES_MAX * DIM];
__device__ __align__(16) bf16   g_xh[(size_t)NODES_MAX * DIM];  // split-bf16 GEMM inputs
__device__ __align__(16) bf16   g_xl[(size_t)NODES_MAX * DIM];
__device__ __align__(16) bf16   g_aggh[(size_t)NODES_MAX * DIM];
__device__ __align__(16) bf16   g_aggl[(size_t)NODES_MAX * DIM];
__device__ __align__(16) bf16   g_hh[(size_t)NODES_MAX * DIM];
__device__ __align__(16) bf16   g_hl[(size_t)NODES_MAX * DIM];
__device__ __align__(16) bf16   g_wth[6 * 16384];               // transposed [N][K] weight hi
__device__ __align__(16) bf16   g_wtl[6 * 16384];               // lo parts

// ---------------- PTX helpers (sm_80-baseline features only) ----------------
__device__ __forceinline__ uint32_t smem_to_u32(const void* p) {
    uint32_t a;
    asm("{ .reg .u64 t; cvta.to.shared.u64 t, %1; cvt.u32.u64 %0, t; }" : "=r"(a) : "l"(p));
    return a;
}
__device__ __forceinline__ void ldsm_x4(uint32_t* r, uint32_t addr) {
    asm volatile("ldmatrix.sync.aligned.m8n8.x4.shared.b16 {%0,%1,%2,%3}, [%4];"
                 : "=r"(r[0]), "=r"(r[1]), "=r"(r[2]), "=r"(r[3]) : "r"(addr));
}
__device__ __forceinline__ void mma_bf16(float* d, const uint32_t* a, const uint32_t* b) {
    asm volatile(
        "mma.sync.aligned.m16n8k16.row.col.f32.bf16.bf16.f32 "
        "{%0,%1,%2,%3}, {%4,%5,%6,%7}, {%8,%9}, {%0,%1,%2,%3};"
        : "+f"(d[0]), "+f"(d[1]), "+f"(d[2]), "+f"(d[3])
        : "r"(a[0]), "r"(a[1]), "r"(a[2]), "r"(a[3]), "r"(b[0]), "r"(b[1]));
}
__device__ __forceinline__ void cp16(uint32_t d, const void* g) {
    asm volatile("cp.async.cg.shared.global [%0], [%1], 16;" :: "r"(d), "l"(g));
}
__device__ __forceinline__ void zero16(uint32_t d) {
    asm volatile("st.shared.v4.b32 [%0], {%1,%1,%1,%1};" :: "r"(d), "r"(0u));
}
#define CP_COMMIT() asm volatile("cp.async.commit_group;" ::: "memory")
#define CP_WAIT1()  asm volatile("cp.async.wait_group 1;" ::: "memory")
#define CP_WAIT0()  asm volatile("cp.async.wait_group 0;" ::: "memory")

// ---------------- CSR build ----------------
__global__ void zero_int_kernel(int* __restrict__ p, int n) {
    int i = blockIdx.x * blockDim.x + threadIdx.x;
    if (i < n) p[i] = 0;
}
__global__ void deg_kernel(const int* __restrict__ dst, int* __restrict__ deg, int E) {
    int e = blockIdx.x * blockDim.x + threadIdx.x;
    if (e < E) atomicAdd(&deg[dst[e]], 1);
}
__global__ void __launch_bounds__(1024)
scan_kernel(const int* __restrict__ cnt, int* __restrict__ rowptr,
            float* __restrict__ inv, int n) {
    __shared__ int wsum[32];
    const int tid = threadIdx.x;
    const int CH = (n + 1023) / 1024;
    const int base = tid * CH;
    int s = 0;
    for (int j = 0; j < CH; ++j) { int i = base + j; if (i < n) s += __ldg(cnt + i); }
    int v = s;
#pragma unroll
    for (int o = 1; o < 32; o <<= 1) { int u = __shfl_up_sync(~0u, v, o); if ((tid & 31) >= o) v += u; }
    if ((tid & 31) == 31) wsum[tid >> 5] = v;
    __syncthreads();
    if (tid < 32) {
        int w = wsum[tid];
#pragma unroll
        for (int o = 1; o < 32; o <<= 1) { int u = __shfl_up_sync(~0u, w, o); if (tid >= o) w += u; }
        wsum[tid] = w;
    }
    __syncthreads();
    int run = (v - s) + ((tid >= 32) ? wsum[(tid >> 5) - 1] : 0);
    for (int j = 0; j < CH; ++j) {
        int i = base + j;
        if (i < n) {
            int c = __ldg(cnt + i);
            run += c;
            rowptr[i + 1] = run;
            inv[i] = 1.0f / (float)max(c, 1);
        }
    }
    if (tid == 0) rowptr[0] = 0;
}
__global__ void fill_csr_kernel(const int* __restrict__ src, const int* __restrict__ dst,
                                const int* __restrict__ rowptr, int* __restrict__ deg,
                                int* __restrict__ csr, int E) {
    int e = blockIdx.x * blockDim.x + threadIdx.x;
    if (e < E) {
        int d = dst[e];
        int cnt = atomicAdd(&deg[d], -1);
        csr[rowptr[d] + cnt - 1] = src[e];
    }
}

// ---------------- split conversions ----------------
__device__ __forceinline__ void split2(float v0, float v1, bf162& hi, bf162& lo) {
    bf16 h0 = __float2bfloat16(v0), h1 = __float2bfloat16(v1);
    bf16 l0 = __float2bfloat16(v0 - __bfloat162float(h0));
    bf16 l1 = __float2bfloat16(v1 - __bfloat162float(h1));
    hi = __halves2bfloat162(h0, h1);
    lo = __halves2bfloat162(l0, l1);
}
__global__ void split_kernel(const float* __restrict__ x, bf16* __restrict__ h,
                             bf16* __restrict__ l, __half* __restrict__ f16, int n2) {
    int i = blockIdx.x * blockDim.x + threadIdx.x;
    if (i < n2) {
        float2 v = reinterpret_cast<const float2*>(x)[i];
        bf162 hi, lo;
        split2(v.x, v.y, hi, lo);
        reinterpret_cast<bf162*>(h)[i] = hi;
        reinterpret_cast<bf162*>(l)[i] = lo;
        reinterpret_cast<__half2*>(f16)[i] = __floats2half2_rn(v.x, v.y);
    }
}
__global__ void wsplit_kernel(const float* W1s, const float* W1n, const float* W2s,
                              const float* W2n, const float* W3s, const float* W3n,
                              bf16* __restrict__ th, bf16* __restrict__ tl) {
    int i = blockIdx.x * blockDim.x + threadIdx.x;
    int m, off;
    if (i < 4 * 16384) { m = i / 16384; off = i % 16384; }
    else {
        int j = i - 4 * 16384;
        if (j >= 2 * 8192) return;
        m = 4 + j / 8192; off = j % 8192;
    }
    const float* src = (m == 0) ? W1s : (m == 1) ? W1n : (m == 2) ? W2s
                     : (m == 3) ? W2n : (m == 4) ? W3s : W3n;
    int Ncols = (m < 4) ? 128 : 64;
    int nn = off / 128, kk = off % 128;
    float v = src[kk * Ncols + nn];
    bf16 h = __float2bfloat16(v);
    th[m * 16384 + off] = h;
    tl[m * 16384 + off] = __float2bfloat16(v - __bfloat162float(h));
}

// -------- atomic-free mean aggregation (fp16 gather, halved traffic -> split bf16 out) --------
__global__ void __launch_bounds__(256)
agg_kernel(const __half* __restrict__ feat, const int* __restrict__ rowptr,
           const int* __restrict__ csr, const float* __restrict__ invdeg,
           bf16* __restrict__ aggh, bf16* __restrict__ aggl, int n) {
    long long t = (long long)blockIdx.x * blockDim.x + threadIdx.x;
    int v = (int)(t >> 5);
    if (v >= n) return;
    int lane = (int)(t & 31);
    const int co = lane * 4;   // 4 fp16 per lane = 8B; 32 lanes cover 128 cols

    int beg = __ldg(rowptr + v);
    int end = __ldg(rowptr + v + 1);

    float ax = 0.f, ay = 0.f, az = 0.f, aw = 0.f;
    int i = beg;
    for (; i + 4 <= end; i += 4) {
        int s0 = __ldg(csr + i + 0);
        int s1 = __ldg(csr + i + 1);
        int s2 = __ldg(csr + i + 2);
        int s3 = __ldg(csr + i + 3);
        uint2 q0 = *reinterpret_cast<const uint2*>(feat + (size_t)s0 * DIM + co);
        uint2 q1 = *reinterpret_cast<const uint2*>(feat + (size_t)s1 * DIM + co);
        uint2 q2 = *reinterpret_cast<const uint2*>(feat + (size_t)s2 * DIM + co);
        uint2 q3 = *reinterpret_cast<const uint2*>(feat + (size_t)s3 * DIM + co);
        float2 a0 = __half22float2(*reinterpret_cast<__half2*>(&q0.x));
        float2 b0 = __half22float2(*reinterpret_cast<__half2*>(&q0.y));
        float2 a1 = __half22float2(*reinterpret_cast<__half2*>(&q1.x));
        float2 b1 = __half22float2(*reinterpret_cast<__half2*>(&q1.y));
        float2 a2 = __half22float2(*reinterpret_cast<__half2*>(&q2.x));
        float2 b2 = __half22float2(*reinterpret_cast<__half2*>(&q2.y));
        float2 a3 = __half22float2(*reinterpret_cast<__half2*>(&q3.x));
        float2 b3 = __half22float2(*reinterpret_cast<__half2*>(&q3.y));
        ax += (a0.x + a1.x) + (a2.x + a3.x);
        ay += (a0.y + a1.y) + (a2.y + a3.y);
        az += (b0.x + b1.x) + (b2.x + b3.x);
        aw += (b0.y + b1.y) + (b2.y + b3.y);
    }
    for (; i < end; ++i) {
        int s0 = __ldg(csr + i);
        uint2 q0 = *reinterpret_cast<const uint2*>(feat + (size_t)s0 * DIM + co);
        float2 a0 = __half22float2(*reinterpret_cast<__half2*>(&q0.x));
        float2 b0 = __half22float2(*reinterpret_cast<__half2*>(&q0.y));
        ax += a0.x; ay += a0.y; az += b0.x; aw += b0.y;
    }
    float sc = __ldg(invdeg + v);
    bf162 h01, l01, h23, l23;
    split2(ax * sc, ay * sc, h01, l01);
    split2(az * sc, aw * sc, h23, l23);
    reinterpret_cast<bf162*>(aggh + (size_t)v * DIM)[lane * 2 + 0] = h01;
    reinterpret_cast<bf162*>(aggh + (size_t)v * DIM)[lane * 2 + 1] = h23;
    reinterpret_cast<bf162*>(aggl + (size_t)v * DIM)[lane * 2 + 0] = l01;
    reinterpret_cast<bf162*>(aggl + (size_t)v * DIM)[lane * 2 + 1] = l23;
}

// ------ layer-3 epilogue: out[v] = S3[v] + invdeg[v] * sum P16[s]  (fp16 gather, 64-wide) ------
__global__ void __launch_bounds__(256)
aggadd_kernel(const float* __restrict__ S, const __half* __restrict__ P,
              const int* __restrict__ rowptr, const int* __restrict__ csr,
              const float* __restrict__ invdeg, float* __restrict__ out, int n) {
    long long t = (long long)blockIdx.x * blockDim.x + threadIdx.x;
    int v = (int)(t >> 5);
    if (v >= n) return;
    int lane = (int)(t & 31);
    const int co = lane * 2;

    int beg = __ldg(rowptr + v);
    int end = __ldg(rowptr + v + 1);

    float sx = 0.f, sy = 0.f;
    int i = beg;
    for (; i + 4 <= end; i += 4) {
        int s0 = __ldg(csr + i + 0);
        int s1 = __ldg(csr + i + 1);
        int s2 = __ldg(csr + i + 2);
        int s3 = __ldg(csr + i + 3);
        float2 p0 = __half22float2(*reinterpret_cast<const __half2*>(P + (size_t)s0 * 64 + co));
        float2 p1 = __half22float2(*reinterpret_cast<const __half2*>(P + (size_t)s1 * 64 + co));
        float2 p2 = __half22float2(*reinterpret_cast<const __half2*>(P + (size_t)s2 * 64 + co));
        float2 p3 = __half22float2(*reinterpret_cast<const __half2*>(P + (size_t)s3 * 64 + co));
        sx += (p0.x + p1.x) + (p2.x + p3.x);
        sy += (p0.y + p1.y) + (p2.y + p3.y);
    }
    for (; i < end; ++i) {
        int s0 = __ldg(csr + i);
        float2 p0 = __half22float2(*reinterpret_cast<const __half2*>(P + (size_t)s0 * 64 + co));
        sx += p0.x; sy += p0.y;
    }
    float sc = __ldg(invdeg + v);
    float2 s3v = *reinterpret_cast<const float2*>(S + (size_t)v * 64 + co);
    *reinterpret_cast<float2*>(out + (size_t)v * 64 + co) =
        make_float2(s3v.x + sc * sx, s3v.y + sc * sy);
}

// ---------------- shared GEMM building blocks ----------------
__device__ __forceinline__ void load_swz(const bf16* __restrict__ g, char* __restrict__ s,
                                         int rows, int t) {
    for (int i = t; i < rows * 16; i += 256) {
        int row = i >> 4, c = i & 15;
        uint4 v = *reinterpret_cast<const uint4*>(g + (size_t)row * 128 + c * 8);
        *reinterpret_cast<uint4*>(s + (size_t)row * 256 + ((c ^ (row & 7)) << 4)) = v;
    }
}
__device__ __forceinline__ void issue_tile4(const bf16* __restrict__ xh, const bf16* __restrict__ xl,
                                            const bf16* __restrict__ gh, const bf16* __restrict__ gl,
                                            int row0, int n, uint32_t stage, int t) {
    int valid = min(32, n - row0);
    for (int i = t; i < 512; i += 256) {
        int row = i >> 4, c = i & 15;
        uint32_t off = (uint32_t)row * 256u + (uint32_t)((c ^ (row & 7)) << 4);
        size_t goff = (size_t)(row0 + row) * 128 + c * 8;
        if (row < valid) {
            cp16(stage + off,          xh + goff);
            cp16(stage + 8192u + off,  xl + goff);
            cp16(stage + 16384u + off, gh + goff);
            cp16(stage + 24576u + off, gl + goff);
        } else {
            zero16(stage + off);          zero16(stage + 8192u + off);
            zero16(stage + 16384u + off); zero16(stage + 24576u + off);
        }
    }
}
__device__ __forceinline__ void issue_tile2(const bf16* __restrict__ xh, const bf16* __restrict__ xl,
                                            int row0, int n, uint32_t stage, int t) {
    int valid = min(32, n - row0);
    for (int i = t; i < 512; i += 256) {
        int row = i >> 4, c = i & 15;
        uint32_t off = (uint32_t)row * 256u + (uint32_t)((c ^ (row & 7)) << 4);
        size_t goff = (size_t)(row0 + row) * 128 + c * 8;
        if (row < valid) {
            cp16(stage + off,         xh + goff);
            cp16(stage + 8192u + off, xl + goff);
        } else {
            zero16(stage + off);
            zero16(stage + 8192u + off);
        }
    }
}

// ---- fused full layer (layer 2): h = relu(X@Ws + b + AGG@Wn) -> fp16 h + bf16 hi/lo ----
template <int NOUT>
__global__ void __launch_bounds__(256, 1)
gemm_kernel(const bf16* __restrict__ xh, const bf16* __restrict__ xl,
            const bf16* __restrict__ gh, const bf16* __restrict__ gl,
            const bf16* __restrict__ wsh, const bf16* __restrict__ wsl,
            const bf16* __restrict__ wnh, const bf16* __restrict__ wnl,
            const float* __restrict__ bias, __half* __restrict__ of16,
            bf16* __restrict__ oh, bf16* __restrict__ ol, int n, int ntiles) {
    extern __shared__ char smem[];
    constexpr int NB = NOUT * 256;
    constexpr int WBASE = 65536;
    constexpr int NPW = NOUT / 4;
    constexpr int NT = NPW / 8;
    const uint32_t sb = smem_to_u32(smem);
    const uint32_t wb = sb + WBASE;
    const int t = threadIdx.x, lane = t & 31, wid = t >> 5;

    load_swz(wsh, smem + WBASE,          NOUT, t);
    load_swz(wsl, smem + WBASE + NB,     NOUT, t);
    load_swz(wnh, smem + WBASE + 2 * NB, NOUT, t);
    load_swz(wnl, smem + WBASE + 3 * NB, NOUT, t);

    const int rhalf = (wid & 1) * 16;
    const int n0 = (wid >> 1) * NPW;
    const int arowl = rhalf + (lane & 15);
    const int akh = lane >> 4;
    const int browl = ((lane >> 4) << 3) + (lane & 7);
    const int bkh = (lane >> 3) & 1;

    float breg[NT][2];
#pragma unroll
    for (int nt = 0; nt < NT; ++nt) {
        int c = n0 + nt * 8 + (lane & 3) * 2;
        breg[nt][0] = __ldg(bias + c);
        breg[nt][1] = __ldg(bias + c + 1);
    }

    int tile = blockIdx.x, buf = 0;
    issue_tile4(xh, xl, gh, gl, tile * 32, n, sb, t);
    CP_COMMIT();

    for (; tile < ntiles; tile += gridDim.x) {
        const int nxt = tile + gridDim.x;
        if (nxt < ntiles) {
            issue_tile4(xh, xl, gh, gl, nxt * 32, n, sb + (uint32_t)(buf ^ 1) * 32768u, t);
            CP_COMMIT();
            CP_WAIT1();
        } else {
            CP_WAIT0();
        }
        __syncthreads();

        const uint32_t ab = sb + (uint32_t)buf * 32768u;
        float acc[NT][4];
#pragma unroll
        for (int q = 0; q < NT; ++q) { acc[q][0] = acc[q][1] = acc[q][2] = acc[q][3] = 0.f; }

#pragma unroll
        for (int ks = 0; ks < 8; ++ks) {
            uint32_t ac = (uint32_t)((2 * ks + akh) ^ (arowl & 7));
            uint32_t aoff = (uint32_t)arowl * 256u + (ac << 4);
            uint32_t Ah[4], Al[4], Gh[4], Gl[4];
            ldsm_x4(Ah, ab + aoff);
            ldsm_x4(Al, ab + 8192u + aoff);
            ldsm_x4(Gh, ab + 16384u + aoff);
            ldsm_x4(Gl, ab + 24576u + aoff);
#pragma unroll
            for (int np = 0; np < NT / 2; ++np) {
                int brow = n0 + np * 16 + browl;
                uint32_t bc = (uint32_t)((2 * ks + bkh) ^ (brow & 7));
                uint32_t boff = (uint32_t)brow * 256u + (bc << 4);
                uint32_t Bsh[4], Bsl[4], Bnh[4], Bnl[4];
                ldsm_x4(Bsh, wb + boff);
                ldsm_x4(Bsl, wb + (uint32_t)NB + boff);
                ldsm_x4(Bnh, wb + (uint32_t)(2 * NB) + boff);
                ldsm_x4(Bnl, wb + (uint32_t)(3 * NB) + boff);
                float* a0 = acc[np * 2];
                float* a1 = acc[np * 2 + 1];
                mma_bf16(a0, Ah, Bsh);  mma_bf16(a1, Ah, Bsh + 2);
                mma_bf16(a0, Gh, Bnh);  mma_bf16(a1, Gh, Bnh + 2);
                mma_bf16(a0, Al, Bsh);  mma_bf16(a1, Al, Bsh + 2);
                mma_bf16(a0, Gl, Bnh);  mma_bf16(a1, Gl, Bnh + 2);
                mma_bf16(a0, Ah, Bsl);  mma_bf16(a1, Ah, Bsl + 2);
                mma_bf16(a0, Gh, Bnl);  mma_bf16(a1, Gh, Bnl + 2);
            }
        }

        const int r0 = tile * 32 + rhalf + (lane >> 2);
        const int r1 = r0 + 8;
#pragma unroll
        for (int nt = 0; nt < NT; ++nt) {
            int c = n0 + nt * 8 + (lane & 3) * 2;
            float v0 = fmaxf(acc[nt][0] + breg[nt][0], 0.f);
            float v1 = fmaxf(acc[nt][1] + breg[nt][1], 0.f);
            float v2 = fmaxf(acc[nt][2] + breg[nt][0], 0.f);
            float v3 = fmaxf(acc[nt][3] + breg[nt][1], 0.f);
            if (r0 < n) {
                *reinterpret_cast<__half2*>(of16 + (size_t)r0 * NOUT + c) = __floats2half2_rn(v0, v1);
                bf162 hi, lo;
                split2(v0, v1, hi, lo);
                *reinterpret_cast<bf162*>(oh + (size_t)r0 * NOUT + c) = hi;
                *reinterpret_cast<bf162*>(ol + (size_t)r0 * NOUT + c) = lo;
            }
            if (r1 < n) {
                *reinterpret_cast<__half2*>(of16 + (size_t)r1 * NOUT + c) = __floats2half2_rn(v2, v3);
                bf162 hi, lo;
                split2(v2, v3, hi, lo);
                *reinterpret_cast<bf162*>(oh + (size_t)r1 * NOUT + c) = hi;
                *reinterpret_cast<bf162*>(ol + (size_t)r1 * NOUT + c) = lo;
            }
        }
        __syncthreads();
        buf ^= 1;
    }
}

// ---- half-layer GEMM (layer 1 split). MODE 0: S = A@W + b (fp32). MODE 1:
//      h = relu(S + A@W) -> fp16 h + bf16 hi/lo. ----
template <int NOUT, int MODE>
__global__ void __launch_bounds__(256, 1)
gemm_half_kernel(const bf16* __restrict__ ah, const bf16* __restrict__ al,
                 const bf16* __restrict__ wh, const bf16* __restrict__ wl,
                 const float* __restrict__ aux, float* __restrict__ outf,
                 __half* __restrict__ of16,
                 bf16* __restrict__ oh, bf16* __restrict__ ol, int n, int ntiles) {
    extern __shared__ char smem[];
    constexpr int NB = NOUT * 256;
    constexpr int WBASE = 32768;
    constexpr int NPW = NOUT / 4;
    constexpr int NT = NPW / 8;
    const uint32_t sb = smem_to_u32(smem);
    const uint32_t wb = sb + WBASE;
    const int t = threadIdx.x, lane = t & 31, wid = t >> 5;

    load_swz(wh, smem + WBASE,      NOUT, t);
    load_swz(wl, smem + WBASE + NB, NOUT, t);

    const int rhalf = (wid & 1) * 16;
    const int n0 = (wid >> 1) * NPW;
    const int arowl = rhalf + (lane & 15);
    const int akh = lane >> 4;
    const int browl = ((lane >> 4) << 3) + (lane & 7);
    const int bkh = (lane >> 3) & 1;

    float breg[NT][2];
    if (MODE == 0) {
#pragma unroll
        for (int nt = 0; nt < NT; ++nt) {
            int c = n0 + nt * 8 + (lane & 3) * 2;
            breg[nt][0] = __ldg(aux + c);
            breg[nt][1] = __ldg(aux + c + 1);
        }
    }

    int tile = blockIdx.x, buf = 0;
    issue_tile2(ah, al, tile * 32, n, sb, t);
    CP_COMMIT();

    for (; tile < ntiles; tile += gridDim.x) {
        const int nxt = tile + gridDim.x;
        if (nxt < ntiles) {
            issue_tile2(ah, al, nxt * 32, n, sb + (uint32_t)(buf ^ 1) * 16384u, t);
            CP_COMMIT();
            CP_WAIT1();
        } else {
            CP_WAIT0();
        }
        __syncthreads();

        const uint32_t ab = sb + (uint32_t)buf * 16384u;
        float acc[NT][4];
#pragma unroll
        for (int q = 0; q < NT; ++q) { acc[q][0] = acc[q][1] = acc[q][2] = acc[q][3] = 0.f; }

#pragma unroll
        for (int ks = 0; ks < 8; ++ks) {
            uint32_t ac = (uint32_t)((2 * ks + akh) ^ (arowl & 7));
            uint32_t aoff = (uint32_t)arowl * 256u + (ac << 4);
            uint32_t Ah[4], Al[4];
            ldsm_x4(Ah, ab + aoff);
            ldsm_x4(Al, ab + 8192u + aoff);
#pragma unroll
            for (int np = 0; np < NT / 2; ++np) {
                int brow = n0 + np * 16 + browl;
                uint32_t bc = (uint32_t)((2 * ks + bkh) ^ (brow & 7));
                uint32_t boff = (uint32_t)brow * 256u + (bc << 4);
                uint32_t Bh[4], Bl[4];
                ldsm_x4(Bh, wb + boff);
                ldsm_x4(Bl, wb + (uint32_t)NB + boff);
                float* a0 = acc[np * 2];
                float* a1 = acc[np * 2 + 1];
                mma_bf16(a0, Ah, Bh);  mma_bf16(a1, Ah, Bh + 2);
                mma_bf16(a0, Al, Bh);  mma_bf16(a1, Al, Bh + 2);
                mma_bf16(a0, Ah, Bl);  mma_bf16(a1, Ah, Bl + 2);
            }
        }

        const int r0 = tile * 32 + rhalf + (lane >> 2);
        const int r1 = r0 + 8;
#pragma unroll
        for (int nt = 0; nt < NT; ++nt) {
            int c = n0 + nt * 8 + (lane & 3) * 2;
            float v0 = acc[nt][0], v1 = acc[nt][1], v2 = acc[nt][2], v3 = acc[nt][3];
            if (MODE == 0) {
                v0 += breg[nt][0]; v1 += breg[nt][1];
                v2 += breg[nt][0]; v3 += breg[nt][1];
                if (r0 < n)
                    *reinterpret_cast<float2*>(outf + (size_t)r0 * NOUT + c) = make_float2(v0, v1);
                if (r1 < n)
                    *reinterpret_cast<float2*>(outf + (size_t)r1 * NOUT + c) = make_float2(v2, v3);
            } else {
                if (r0 < n) {
                    float2 s = *reinterpret_cast<const float2*>(aux + (size_t)r0 * NOUT + c);
                    v0 = fmaxf(v0 + s.x, 0.f); v1 = fmaxf(v1 + s.y, 0.f);
                    *reinterpret_cast<__half2*>(of16 + (size_t)r0 * NOUT + c) = __floats2half2_rn(v0, v1);
                    bf162 hi, lo;
                    split2(v0, v1, hi, lo);
                    *reinterpret_cast<bf162*>(oh + (size_t)r0 * NOUT + c) = hi;
                    *reinterpret_cast<bf162*>(ol + (size_t)r0 * NOUT + c) = lo;
                }
                if (r1 < n) {
                    float2 s = *reinterpret_cast<const float2*>(aux + (size_t)r1 * NOUT + c);
                    v2 = fmaxf(v2 + s.x, 0.f); v3 = fmaxf(v3 + s.y, 0.f);
                    *reinterpret_cast<__half2*>(of16 + (size_t)r1 * NOUT + c) = __floats2half2_rn(v2, v3);
                    bf162 hi, lo;
                    split2(v2, v3, hi, lo);
                    *reinterpret_cast<bf162*>(oh + (size_t)r1 * NOUT + c) = hi;
                    *reinterpret_cast<bf162*>(ol + (size_t)r1 * NOUT + c) = lo;
                }
            }
        }
        __syncthreads();
        buf ^= 1;
    }
}

// ---- layer-3 dual GEMM: S = X@Ws + b (fp32), P = X@Wn (fp16), A tiles loaded once ----
__global__ void __launch_bounds__(256, 1)
gemm3_dual_kernel(const bf16* __restrict__ xh, const bf16* __restrict__ xl,
                  const bf16* __restrict__ wsh, const bf16* __restrict__ wsl,
                  const bf16* __restrict__ wnh, const bf16* __restrict__ wnl,
                  const float* __restrict__ bias, float* __restrict__ S,
                  __half* __restrict__ P, int n, int ntiles) {
    extern __shared__ char smem[];
    constexpr int NB = 64 * 256;
    constexpr int WBASE = 32768;
    const uint32_t sb = smem_to_u32(smem);
    const uint32_t wb = sb + WBASE;
    const int t = threadIdx.x, lane = t & 31, wid = t >> 5;

    load_swz(wsh, smem + WBASE,          64, t);
    load_swz(wsl, smem + WBASE + NB,     64, t);
    load_swz(wnh, smem + WBASE + 2 * NB, 64, t);
    load_swz(wnl, smem + WBASE + 3 * NB, 64, t);

    const int rhalf = (wid & 1) * 16;
    const int n0 = (wid >> 1) * 16;
    const int arowl = rhalf + (lane & 15);
    const int akh = lane >> 4;
    const int browl = ((lane >> 4) << 3) + (lane & 7);
    const int bkh = (lane >> 3) & 1;
    const int brow = n0 + browl;

    float breg[2][2];
#pragma unroll
    for (int nt = 0; nt < 2; ++nt) {
        int c = n0 + nt * 8 + (lane & 3) * 2;
        breg[nt][0] = __ldg(bias + c);
        breg[nt][1] = __ldg(bias + c + 1);
    }

    int tile = blockIdx.x, buf = 0;
    issue_tile2(xh, xl, tile * 32, n, sb, t);
    CP_COMMIT();

    for (; tile < ntiles; tile += gridDim.x) {
        const int nxt = tile + gridDim.x;
        if (nxt < ntiles) {
            issue_tile2(xh, xl, nxt * 32, n, sb + (uint32_t)(buf ^ 1) * 16384u, t);
            CP_COMMIT();
            CP_WAIT1();
        } else {
            CP_WAIT0();
        }
        __syncthreads();

        const uint32_t ab = sb + (uint32_t)buf * 16384u;
        float accS[2][4], accP[2][4];
#pragma unroll
        for (int q = 0; q < 2; ++q) {
            accS[q][0] = accS[q][1] = accS[q][2] = accS[q][3] = 0.f;
            accP[q][0] = accP[q][1] = accP[q][2] = accP[q][3] = 0.f;
        }

#pragma unroll
        for (int ks = 0; ks < 8; ++ks) {
            uint32_t ac = (uint32_t)((2 * ks + akh) ^ (arowl & 7));
            uint32_t aoff = (uint32_t)arowl * 256u + (ac << 4);
            uint32_t Ah[4], Al[4];
            ldsm_x4(Ah, ab + aoff);
            ldsm_x4(Al, ab + 8192u + aoff);
            uint32_t bc = (uint32_t)((2 * ks + bkh) ^ (brow & 7));
            uint32_t boff = (uint32_t)brow * 256u + (bc << 4);
            uint32_t Bsh[4], Bsl[4], Bnh[4], Bnl[4];
            ldsm_x4(Bsh, wb + boff);
            ldsm_x4(Bsl, wb + (uint32_t)NB + boff);
            ldsm_x4(Bnh, wb + (uint32_t)(2 * NB) + boff);
            ldsm_x4(Bnl, wb + (uint32_t)(3 * NB) + boff);
            mma_bf16(accS[0], Ah, Bsh);  mma_bf16(accS[1], Ah, Bsh + 2);
            mma_bf16(accP[0], Ah, Bnh);  mma_bf16(accP[1], Ah, Bnh + 2);
            mma_bf16(accS[0], Al, Bsh);  mma_bf16(accS[1], Al, Bsh + 2);
            mma_bf16(accP[0], Al, Bnh);  mma_bf16(accP[1], Al, Bnh + 2);
            mma_bf16(accS[0], Ah, Bsl);  mma_bf16(accS[1], Ah, Bsl + 2);
            mma_bf16(accP[0], Ah, Bnl);  mma_bf16(accP[1], Ah, Bnl + 2);
        }

        const int r0 = tile * 32 + rhalf + (lane >> 2);
        const int r1 = r0 + 8;
#pragma unroll
        for (int nt = 0; nt < 2; ++nt) {
            int c = n0 + nt * 8 + (lane & 3) * 2;
            if (r0 < n) {
                *reinterpret_cast<float2*>(S + (size_t)r0 * 64 + c) =
                    make_float2(accS[nt][0] + breg[nt][0], accS[nt][1] + breg[nt][1]);
                *reinterpret_cast<__half2*>(P + (size_t)r0 * 64 + c) =
                    __floats2half2_rn(accP[nt][0], accP[nt][1]);
            }
            if (r1 < n) {
                *reinterpret_cast<float2*>(S + (size_t)r1 * 64 + c) =
                    make_float2(accS[nt][2] + breg[nt][0], accS[nt][3] + breg[nt][1]);
                *reinterpret_cast<__half2*>(P + (size_t)r1 * 64 + c) =
                    __floats2half2_rn(accP[nt][2], accP[nt][3]);
            }
        }
        __syncthreads();
        buf ^= 1;
    }
}

// ---------------- launch ----------------
extern "C" void kernel_launch(void* const* d_in, const int* in_sizes, int n_in,
                              void* d_out, int out_size) {
    const float* x   = (const float*)d_in[0];
    const int*   src = (const int*)d_in[1];
    const int*   dst = (const int*)d_in[2];
    const float* Ws1 = (const float*)d_in[3];
    const float* b1  = (const float*)d_in[4];
    const float* Wn1 = (const float*)d_in[5];
    const float* Ws2 = (const float*)d_in[6];
    const float* b2  = (const float*)d_in[7];
    const float* Wn2 = (const float*)d_in[8];
    const float* Ws3 = (const float*)d_in[9];
    const float* b3  = (const float*)d_in[10];
    const float* Wn3 = (const float*)d_in[11];

    const int N = in_sizes[0] / DIM;
    const int E = in_sizes[1];
    float* out = (float*)d_out;

    int *deg_i, *rowptr, *csr;
    float *invdeg, *S1, *S3;
    __half *P16, *xf16, *hf16;
    bf16 *xh, *xl, *aggh, *aggl, *hh, *hl, *wth, *wtl;
    cudaGetSymbolAddress((void**)&deg_i,  g_deg_i);
    cudaGetSymbolAddress((void**)&rowptr, g_rowptr);
    cudaGetSymbolAddress((void**)&csr,    g_csr);
    cudaGetSymbolAddress((void**)&invdeg, g_invdeg);
    cudaGetSymbolAddress((void**)&S1,     g_S1);
    cudaGetSymbolAddress((void**)&S3,     g_S3);
    cudaGetSymbolAddress((void**)&P16,    g_P16);
    cudaGetSymbolAddress((void**)&xf16,   g_xf16);
    cudaGetSymbolAddress((void**)&hf16,   g_hf16);
    cudaGetSymbolAddress((void**)&xh,     g_xh);
    cudaGetSymbolAddress((void**)&xl,     g_xl);
    cudaGetSymbolAddress((void**)&aggh,   g_aggh);
    cudaGetSymbolAddress((void**)&aggl,   g_aggl);
    cudaGetSymbolAddress((void**)&hh,     g_hh);
    cudaGetSymbolAddress((void**)&hl,     g_hl);
    cudaGetSymbolAddress((void**)&wth,    g_wth);
    cudaGetSymbolAddress((void**)&wtl,    g_wtl);

    // one-time host-side setup (runs on the non-captured correctness call first)
    static cudaStream_t s1 = nullptr;
    static cudaEvent_t evf, evsp, ea1;
    if (!s1) {
        cudaStreamCreateWithFlags(&s1, cudaStreamNonBlocking);
        cudaEventCreateWithFlags(&evf,  cudaEventDisableTiming);
        cudaEventCreateWithFlags(&evsp, cudaEventDisableTiming);
        cudaEventCreateWithFlags(&ea1,  cudaEventDisableTiming);
    }

    const int SM128 = 65536 + 4 * 128 * 256;  // 196608 (fused layer 2)
    const int SMH   = 32768 + 2 * 128 * 256;  // 98304  (half GEMMs, layer 1)
    const int SM3   = 32768 + 4 * 64 * 256;   // 98304  (layer-3 dual)
    cudaFuncSetAttribute(gemm_kernel<128>,
                         cudaFuncAttributeMaxDynamicSharedMemorySize, SM128);
    cudaFuncSetAttribute(gemm_half_kernel<128, 0>,
                         cudaFuncAttributeMaxDynamicSharedMemorySize, SMH);
    cudaFuncSetAttribute(gemm_half_kernel<128, 1>,
                         cudaFuncAttributeMaxDynamicSharedMemorySize, SMH);
    cudaFuncSetAttribute(gemm3_dual_kernel,
                         cudaFuncAttributeMaxDynamicSharedMemorySize, SM3);

    const int nb_nodes = (N + 255) / 256;
    const int nb_edges = (E + 255) / 256;
    const int nb_agg   = (int)(((long long)N * 32 + 255) / 256);
    const int ntiles   = (N + 31) / 32;
    const int GRID     = 152;

    // ---- fork: s1 builds CSR while s0 does splits; agg1 (s1) waits on the split ----
    cudaEventRecord(evf, 0);
    cudaStreamWaitEvent(s1, evf, 0);

    zero_int_kernel<<<nb_nodes, 256, 0, s1>>>(deg_i, N);
    deg_kernel<<<nb_edges, 256, 0, s1>>>(dst, deg_i, E);
    scan_kernel<<<1, 1024, 0, s1>>>(deg_i, rowptr, invdeg, N);
    fill_csr_kernel<<<nb_edges, 256, 0, s1>>>(src, dst, rowptr, deg_i, csr, E);

    split_kernel<<<(N * DIM / 2 + 255) / 256, 256>>>(x, xh, xl, xf16, N * DIM / 2);
    cudaEventRecord(evsp, 0);
    wsplit_kernel<<<(81920 + 255) / 256, 256>>>(Ws1, Wn1, Ws2, Wn2, Ws3, Wn3, wth, wtl);

    cudaStreamWaitEvent(s1, evsp, 0);
    agg_kernel<<<nb_agg, 256, 0, s1>>>(xf16, rowptr, csr, invdeg, aggh, aggl, N);
    cudaEventRecord(ea1, s1);

    // s0: layer-1 self GEMM overlaps with CSR + agg1
    gemm_half_kernel<128, 0><<<GRID, 256, SMH>>>(
        xh, xl, wth + 0 * 16384, wtl + 0 * 16384, b1, S1, nullptr, nullptr, nullptr, N, ntiles);

    // ---- join: layer-1 neigh + the rest run single-stream ----
    cudaStreamWaitEvent(0, ea1, 0);
    gemm_half_kernel<128, 1><<<GRID, 256, SMH>>>(
        aggh, aggl, wth + 1 * 16384, wtl + 1 * 16384, S1, nullptr, hf16, hh, hl, N, ntiles);

    // Layer 2 (fused)
    agg_kernel<<<nb_agg, 256>>>(hf16, rowptr, csr, invdeg, aggh, aggl, N);
    gemm_kernel<128><<<GRID, 256, SM128>>>(
        hh, hl, aggh, aggl,
        wth + 2 * 16384, wtl + 2 * 16384, wth + 3 * 16384, wtl + 3 * 16384,
        b2, hf16, hh, hl, N, ntiles);

    // Layer 3: lin-before-mp (matches reference); P in fp16 halves the gather
    gemm3_dual_kernel<<<GRID, 256, SM3>>>(
        hh, hl,
        wth + 4 * 16384, wtl + 4 * 16384, wth + 5 * 16384, wtl + 5 * 16384,
        b3, S3, P16, N, ntiles);
    aggadd_kernel<<<nb_agg, 256>>>(S3, P16, rowptr, csr, invdeg, out, N);
}

// round 12
// speedup vs baseline: 1.3428x; 1.1626x over previous
#include <cuda_runtime.h>
#include <cuda_fp16.h>
#include <cstdint>

#define DIM 128
#define NODES_MAX 50048
#define EDGES_MAX 800000

// ---------------- device scratch (allocation-free rule) ----------------
__device__ int   g_deg_i[NODES_MAX];
__device__ int   g_rowptr[NODES_MAX + 1];
__device__ int   g_csr[EDGES_MAX];
__device__ float g_invdeg[NODES_MAX];
__device__ __align__(16) float  g_S1[(size_t)NODES_MAX * DIM];  // layer-1 self partial (fp32)
__device__ __align__(16) float  g_S3[(size_t)NODES_MAX * 64];   // layer-3 self partial (fp32)
__device__ __align__(16) __half g_P16[(size_t)NODES_MAX * 64];  // layer-3 h@Wn3 (fp16)
__device__ __align__(16) __half g_xf16[(size_t)NODES_MAX * DIM];// fp16 activations
__device__ __align__(16) __half g_hf16[(size_t)NODES_MAX * DIM];
__device__ __align__(16) __half g_agg16[(size_t)NODES_MAX * DIM];
__device__ __align__(16) __half g_wth[6 * 16384];               // transposed [N][K] weight hi (fp16)
__device__ __align__(16) __half g_wtl[6 * 16384];               // lo parts (fp16)

// ---------------- PTX helpers (sm_80-baseline features only) ----------------
__device__ __forceinline__ uint32_t smem_to_u32(const void* p) {
    uint32_t a;
    asm("{ .reg .u64 t; cvta.to.shared.u64 t, %1; cvt.u32.u64 %0, t; }" : "=r"(a) : "l"(p));
    return a;
}
__device__ __forceinline__ void ldsm_x4(uint32_t* r, uint32_t addr) {
    asm volatile("ldmatrix.sync.aligned.m8n8.x4.shared.b16 {%0,%1,%2,%3}, [%4];"
                 : "=r"(r[0]), "=r"(r[1]), "=r"(r[2]), "=r"(r[3]) : "r"(addr));
}
__device__ __forceinline__ void mma_f16(float* d, const uint32_t* a, const uint32_t* b) {
    asm volatile(
        "mma.sync.aligned.m16n8k16.row.col.f32.f16.f16.f32 "
        "{%0,%1,%2,%3}, {%4,%5,%6,%7}, {%8,%9}, {%0,%1,%2,%3};"
        : "+f"(d[0]), "+f"(d[1]), "+f"(d[2]), "+f"(d[3])
        : "r"(a[0]), "r"(a[1]), "r"(a[2]), "r"(a[3]), "r"(b[0]), "r"(b[1]));
}
__device__ __forceinline__ void cp16(uint32_t d, const void* g) {
    asm volatile("cp.async.cg.shared.global [%0], [%1], 16;" :: "r"(d), "l"(g));
}
__device__ __forceinline__ void zero16(uint32_t d) {
    asm volatile("st.shared.v4.b32 [%0], {%1,%1,%1,%1};" :: "r"(d), "r"(0u));
}
#define CP_COMMIT() asm volatile("cp.async.commit_group;" ::: "memory")
#define CP_WAIT1()  asm volatile("cp.async.wait_group 1;" ::: "memory")
#define CP_WAIT0()  asm volatile("cp.async.wait_group 0;" ::: "memory")

// ---------------- CSR build ----------------
__global__ void zero_int_kernel(int* __restrict__ p, int n) {
    int i = blockIdx.x * blockDim.x + threadIdx.x;
    if (i < n) p[i] = 0;
}
__global__ void deg_kernel(const int* __restrict__ dst, int* __restrict__ deg, int E) {
    int e = blockIdx.x * blockDim.x + threadIdx.x;
    if (e < E) atomicAdd(&deg[dst[e]], 1);
}
__global__ void __launch_bounds__(1024)
scan_kernel(const int* __restrict__ cnt, int* __restrict__ rowptr,
            float* __restrict__ inv, int n) {
    __shared__ int wsum[32];
    const int tid = threadIdx.x;
    const int CH = (n + 1023) / 1024;
    const int base = tid * CH;
    int s = 0;
    for (int j = 0; j < CH; ++j) { int i = base + j; if (i < n) s += __ldg(cnt + i); }
    int v = s;
#pragma unroll
    for (int o = 1; o < 32; o <<= 1) { int u = __shfl_up_sync(~0u, v, o); if ((tid & 31) >= o) v += u; }
    if ((tid & 31) == 31) wsum[tid >> 5] = v;
    __syncthreads();
    if (tid < 32) {
        int w = wsum[tid];
#pragma unroll
        for (int o = 1; o < 32; o <<= 1) { int u = __shfl_up_sync(~0u, w, o); if (tid >= o) w += u; }
        wsum[tid] = w;
    }
    __syncthreads();
    int run = (v - s) + ((tid >= 32) ? wsum[(tid >> 5) - 1] : 0);
    for (int j = 0; j < CH; ++j) {
        int i = base + j;
        if (i < n) {
            int c = __ldg(cnt + i);
            run += c;
            rowptr[i + 1] = run;
            inv[i] = 1.0f / (float)max(c, 1);
        }
    }
    if (tid == 0) rowptr[0] = 0;
}
__global__ void fill_csr_kernel(const int* __restrict__ src, const int* __restrict__ dst,
                                const int* __restrict__ rowptr, int* __restrict__ deg,
                                int* __restrict__ csr, int E) {
    int e = blockIdx.x * blockDim.x + threadIdx.x;
    if (e < E) {
        int d = dst[e];
        int cnt = atomicAdd(&deg[d], -1);
        csr[rowptr[d] + cnt - 1] = src[e];
    }
}

// ---------------- conversions ----------------
__global__ void split_kernel(const float* __restrict__ x, __half* __restrict__ f16, int n2) {
    int i = blockIdx.x * blockDim.x + threadIdx.x;
    if (i < n2) {
        float2 v = reinterpret_cast<const float2*>(x)[i];
        reinterpret_cast<__half2*>(f16)[i] = __floats2half2_rn(v.x, v.y);
    }
}
// weights: transpose to [N][K], fp16 hi/lo split (combined error ~2^-22)
__global__ void wsplit_kernel(const float* W1s, const float* W1n, const float* W2s,
                              const float* W2n, const float* W3s, const float* W3n,
                              __half* __restrict__ th, __half* __restrict__ tl) {
    int i = blockIdx.x * blockDim.x + threadIdx.x;
    int m, off;
    if (i < 4 * 16384) { m = i / 16384; off = i % 16384; }
    else {
        int j = i - 4 * 16384;
        if (j >= 2 * 8192) return;
        m = 4 + j / 8192; off = j % 8192;
    }
    const float* src = (m == 0) ? W1s : (m == 1) ? W1n : (m == 2) ? W2s
                     : (m == 3) ? W2n : (m == 4) ? W3s : W3n;
    int Ncols = (m < 4) ? 128 : 64;
    int nn = off / 128, kk = off % 128;
    float v = src[kk * Ncols + nn];
    __half h = __float2half(v);
    th[m * 16384 + off] = h;
    tl[m * 16384 + off] = __float2half(v - __half2float(h));
}

// -------- atomic-free mean aggregation (fp16 gather, fp32 accumulate, fp16 out) --------
__global__ void __launch_bounds__(256)
agg_kernel(const __half* __restrict__ feat, const int* __restrict__ rowptr,
           const int* __restrict__ csr, const float* __restrict__ invdeg,
           __half* __restrict__ agg, int n) {
    long long t = (long long)blockIdx.x * blockDim.x + threadIdx.x;
    int v = (int)(t >> 5);
    if (v >= n) return;
    int lane = (int)(t & 31);
    const int co = lane * 4;

    int beg = __ldg(rowptr + v);
    int end = __ldg(rowptr + v + 1);

    float ax = 0.f, ay = 0.f, az = 0.f, aw = 0.f;
    int i = beg;
    for (; i + 4 <= end; i += 4) {
        int s0 = __ldg(csr + i + 0);
        int s1 = __ldg(csr + i + 1);
        int s2 = __ldg(csr + i + 2);
        int s3 = __ldg(csr + i + 3);
        uint2 q0 = *reinterpret_cast<const uint2*>(feat + (size_t)s0 * DIM + co);
        uint2 q1 = *reinterpret_cast<const uint2*>(feat + (size_t)s1 * DIM + co);
        uint2 q2 = *reinterpret_cast<const uint2*>(feat + (size_t)s2 * DIM + co);
        uint2 q3 = *reinterpret_cast<const uint2*>(feat + (size_t)s3 * DIM + co);
        float2 a0 = __half22float2(*reinterpret_cast<__half2*>(&q0.x));
        float2 b0 = __half22float2(*reinterpret_cast<__half2*>(&q0.y));
        float2 a1 = __half22float2(*reinterpret_cast<__half2*>(&q1.x));
        float2 b1 = __half22float2(*reinterpret_cast<__half2*>(&q1.y));
        float2 a2 = __half22float2(*reinterpret_cast<__half2*>(&q2.x));
        float2 b2 = __half22float2(*reinterpret_cast<__half2*>(&q2.y));
        float2 a3 = __half22float2(*reinterpret_cast<__half2*>(&q3.x));
        float2 b3 = __half22float2(*reinterpret_cast<__half2*>(&q3.y));
        ax += (a0.x + a1.x) + (a2.x + a3.x);
        ay += (a0.y + a1.y) + (a2.y + a3.y);
        az += (b0.x + b1.x) + (b2.x + b3.x);
        aw += (b0.y + b1.y) + (b2.y + b3.y);
    }
    for (; i < end; ++i) {
        int s0 = __ldg(csr + i);
        uint2 q0 = *reinterpret_cast<const uint2*>(feat + (size_t)s0 * DIM + co);
        float2 a0 = __half22float2(*reinterpret_cast<__half2*>(&q0.x));
        float2 b0 = __half22float2(*reinterpret_cast<__half2*>(&q0.y));
        ax += a0.x; ay += a0.y; az += b0.x; aw += b0.y;
    }
    float sc = __ldg(invdeg + v);
    reinterpret_cast<__half2*>(agg + (size_t)v * DIM)[lane * 2 + 0] = __floats2half2_rn(ax * sc, ay * sc);
    reinterpret_cast<__half2*>(agg + (size_t)v * DIM)[lane * 2 + 1] = __floats2half2_rn(az * sc, aw * sc);
}

// ------ layer-3 epilogue: out[v] = S3[v] + invdeg[v] * sum P16[s]  (fp16 gather, 64-wide) ------
__global__ void __launch_bounds__(256)
aggadd_kernel(const float* __restrict__ S, const __half* __restrict__ P,
              const int* __restrict__ rowptr, const int* __restrict__ csr,
              const float* __restrict__ invdeg, float* __restrict__ out, int n) {
    long long t = (long long)blockIdx.x * blockDim.x + threadIdx.x;
    int v = (int)(t >> 5);
    if (v >= n) return;
    int lane = (int)(t & 31);
    const int co = lane * 2;

    int beg = __ldg(rowptr + v);
    int end = __ldg(rowptr + v + 1);

    float sx = 0.f, sy = 0.f;
    int i = beg;
    for (; i + 4 <= end; i += 4) {
        int s0 = __ldg(csr + i + 0);
        int s1 = __ldg(csr + i + 1);
        int s2 = __ldg(csr + i + 2);
        int s3 = __ldg(csr + i + 3);
        float2 p0 = __half22float2(*reinterpret_cast<const __half2*>(P + (size_t)s0 * 64 + co));
        float2 p1 = __half22float2(*reinterpret_cast<const __half2*>(P + (size_t)s1 * 64 + co));
        float2 p2 = __half22float2(*reinterpret_cast<const __half2*>(P + (size_t)s2 * 64 + co));
        float2 p3 = __half22float2(*reinterpret_cast<const __half2*>(P + (size_t)s3 * 64 + co));
        sx += (p0.x + p1.x) + (p2.x + p3.x);
        sy += (p0.y + p1.y) + (p2.y + p3.y);
    }
    for (; i < end; ++i) {
        int s0 = __ldg(csr + i);
        float2 p0 = __half22float2(*reinterpret_cast<const __half2*>(P + (size_t)s0 * 64 + co));
        sx += p0.x; sy += p0.y;
    }
    float sc = __ldg(invdeg + v);
    float2 s3v = *reinterpret_cast<const float2*>(S + (size_t)v * 64 + co);
    *reinterpret_cast<float2*>(out + (size_t)v * 64 + co) =
        make_float2(s3v.x + sc * sx, s3v.y + sc * sy);
}

// ---------------- shared GEMM building blocks ----------------
__device__ __forceinline__ void load_swz(const __half* __restrict__ g, char* __restrict__ s,
                                         int rows, int t) {
    for (int i = t; i < rows * 16; i += 256) {
        int row = i >> 4, c = i & 15;
        uint4 v = *reinterpret_cast<const uint4*>(g + (size_t)row * 128 + c * 8);
        *reinterpret_cast<uint4*>(s + (size_t)row * 256 + ((c ^ (row & 7)) << 4)) = v;
    }
}
// one fp16 activation array per tile (8KB)
__device__ __forceinline__ void issue_1(const __half* __restrict__ a,
                                        int row0, int n, uint32_t stage, int t) {
    int valid = min(32, n - row0);
    for (int i = t; i < 512; i += 256) {
        int row = i >> 4, c = i & 15;
        uint32_t off = (uint32_t)row * 256u + (uint32_t)((c ^ (row & 7)) << 4);
        size_t goff = (size_t)(row0 + row) * 128 + c * 8;
        if (row < valid) cp16(stage + off, a + goff);
        else             zero16(stage + off);
    }
}
// two fp16 arrays (x @ 0, g @ 8192)
__device__ __forceinline__ void issue_2(const __half* __restrict__ xf, const __half* __restrict__ gf,
                                        int row0, int n, uint32_t stage, int t) {
    int valid = min(32, n - row0);
    for (int i = t; i < 512; i += 256) {
        int row = i >> 4, c = i & 15;
        uint32_t off = (uint32_t)row * 256u + (uint32_t)((c ^ (row & 7)) << 4);
        size_t goff = (size_t)(row0 + row) * 128 + c * 8;
        if (row < valid) {
            cp16(stage + off,         xf + goff);
            cp16(stage + 8192u + off, gf + goff);
        } else {
            zero16(stage + off);
            zero16(stage + 8192u + off);
        }
    }
}

// ---- fused full layer (layer 2): h = relu(X@Ws + b + AGG@Wn) -> fp16 h ----
// smem: stages 2 x 16KB (x+agg) @0/16384; weights @32768 (4 arrays x 32KB).
template <int NOUT>
__global__ void __launch_bounds__(256, 1)
gemm_kernel(const __half* __restrict__ xf, const __half* __restrict__ gf,
            const __half* __restrict__ wsh, const __half* __restrict__ wsl,
            const __half* __restrict__ wnh, const __half* __restrict__ wnl,
            const float* __restrict__ bias, __half* __restrict__ of16,
            int n, int ntiles) {
    extern __shared__ char smem[];
    constexpr int NB = NOUT * 256;
    constexpr int WBASE = 32768;
    constexpr int NPW = NOUT / 4;
    constexpr int NT = NPW / 8;
    const uint32_t sb = smem_to_u32(smem);
    const uint32_t wb = sb + WBASE;
    const int t = threadIdx.x, lane = t & 31, wid = t >> 5;

    load_swz(wsh, smem + WBASE,          NOUT, t);
    load_swz(wsl, smem + WBASE + NB,     NOUT, t);
    load_swz(wnh, smem + WBASE + 2 * NB, NOUT, t);
    load_swz(wnl, smem + WBASE + 3 * NB, NOUT, t);

    const int rhalf = (wid & 1) * 16;
    const int n0 = (wid >> 1) * NPW;
    const int arowl = rhalf + (lane & 15);
    const int akh = lane >> 4;
    const int browl = ((lane >> 4) << 3) + (lane & 7);
    const int bkh = (lane >> 3) & 1;

    float breg[NT][2];
#pragma unroll
    for (int nt = 0; nt < NT; ++nt) {
        int c = n0 + nt * 8 + (lane & 3) * 2;
        breg[nt][0] = __ldg(bias + c);
        breg[nt][1] = __ldg(bias + c + 1);
    }

    int tile = blockIdx.x, buf = 0;
    issue_2(xf, gf, tile * 32, n, sb, t);
    CP_COMMIT();

    for (; tile < ntiles; tile += gridDim.x) {
        const int nxt = tile + gridDim.x;
        if (nxt < ntiles) {
            issue_2(xf, gf, nxt * 32, n, sb + (uint32_t)(buf ^ 1) * 16384u, t);
            CP_COMMIT();
            CP_WAIT1();
        } else {
            CP_WAIT0();
        }
        __syncthreads();

        const uint32_t ab = sb + (uint32_t)buf * 16384u;
        float acc[NT][4];
#pragma unroll
        for (int q = 0; q < NT; ++q) { acc[q][0] = acc[q][1] = acc[q][2] = acc[q][3] = 0.f; }

#pragma unroll
        for (int ks = 0; ks < 8; ++ks) {
            uint32_t ac = (uint32_t)((2 * ks + akh) ^ (arowl & 7));
            uint32_t aoff = (uint32_t)arowl * 256u + (ac << 4);
            uint32_t Ax[4], Ag[4];
            ldsm_x4(Ax, ab + aoff);
            ldsm_x4(Ag, ab + 8192u + aoff);
#pragma unroll
            for (int np = 0; np < NT / 2; ++np) {
                int brow = n0 + np * 16 + browl;
                uint32_t bc = (uint32_t)((2 * ks + bkh) ^ (brow & 7));
                uint32_t boff = (uint32_t)brow * 256u + (bc << 4);
                uint32_t Bsh[4], Bsl[4], Bnh[4], Bnl[4];
                ldsm_x4(Bsh, wb + boff);
                ldsm_x4(Bsl, wb + (uint32_t)NB + boff);
                ldsm_x4(Bnh, wb + (uint32_t)(2 * NB) + boff);
                ldsm_x4(Bnl, wb + (uint32_t)(3 * NB) + boff);
                float* a0 = acc[np * 2];
                float* a1 = acc[np * 2 + 1];
                mma_f16(a0, Ax, Bsh);  mma_f16(a1, Ax, Bsh + 2);
                mma_f16(a0, Ag, Bnh);  mma_f16(a1, Ag, Bnh + 2);
                mma_f16(a0, Ax, Bsl);  mma_f16(a1, Ax, Bsl + 2);
                mma_f16(a0, Ag, Bnl);  mma_f16(a1, Ag, Bnl + 2);
            }
        }

        const int r0 = tile * 32 + rhalf + (lane >> 2);
        const int r1 = r0 + 8;
#pragma unroll
        for (int nt = 0; nt < NT; ++nt) {
            int c = n0 + nt * 8 + (lane & 3) * 2;
            float v0 = fmaxf(acc[nt][0] + breg[nt][0], 0.f);
            float v1 = fmaxf(acc[nt][1] + breg[nt][1], 0.f);
            float v2 = fmaxf(acc[nt][2] + breg[nt][0], 0.f);
            float v3 = fmaxf(acc[nt][3] + breg[nt][1], 0.f);
            if (r0 < n)
                *reinterpret_cast<__half2*>(of16 + (size_t)r0 * NOUT + c) = __floats2half2_rn(v0, v1);
            if (r1 < n)
                *reinterpret_cast<__half2*>(of16 + (size_t)r1 * NOUT + c) = __floats2half2_rn(v2, v3);
        }
        __syncthreads();
        buf ^= 1;
    }
}

// ---- half-layer GEMM. MODE 0: S = A@W + b (fp32). MODE 1: h = relu(S + A@W) -> fp16 ----
template <int NOUT, int MODE>
__global__ void __launch_bounds__(256, 1)
gemm_half_kernel(const __half* __restrict__ af, const __half* __restrict__ wh,
                 const __half* __restrict__ wl, const float* __restrict__ aux,
                 float* __restrict__ outf, __half* __restrict__ of16, int n, int ntiles) {
    extern __shared__ char smem[];
    constexpr int NB = NOUT * 256;
    constexpr int WBASE = 16384;
    constexpr int NPW = NOUT / 4;
    constexpr int NT = NPW / 8;
    const uint32_t sb = smem_to_u32(smem);
    const uint32_t wb = sb + WBASE;
    const int t = threadIdx.x, lane = t & 31, wid = t >> 5;

    load_swz(wh, smem + WBASE,      NOUT, t);
    load_swz(wl, smem + WBASE + NB, NOUT, t);

    const int rhalf = (wid & 1) * 16;
    const int n0 = (wid >> 1) * NPW;
    const int arowl = rhalf + (lane & 15);
    const int akh = lane >> 4;
    const int browl = ((lane >> 4) << 3) + (lane & 7);
    const int bkh = (lane >> 3) & 1;

    float breg[NT][2];
    if (MODE == 0) {
#pragma unroll
        for (int nt = 0; nt < NT; ++nt) {
            int c = n0 + nt * 8 + (lane & 3) * 2;
            breg[nt][0] = __ldg(aux + c);
            breg[nt][1] = __ldg(aux + c + 1);
        }
    }

    int tile = blockIdx.x, buf = 0;
    issue_1(af, tile * 32, n, sb, t);
    CP_COMMIT();

    for (; tile < ntiles; tile += gridDim.x) {
        const int nxt = tile + gridDim.x;
        if (nxt < ntiles) {
            issue_1(af, nxt * 32, n, sb + (uint32_t)(buf ^ 1) * 8192u, t);
            CP_COMMIT();
            CP_WAIT1();
        } else {
            CP_WAIT0();
        }
        __syncthreads();

        const uint32_t ab = sb + (uint32_t)buf * 8192u;
        float acc[NT][4];
#pragma unroll
        for (int q = 0; q < NT; ++q) { acc[q][0] = acc[q][1] = acc[q][2] = acc[q][3] = 0.f; }

#pragma unroll
        for (int ks = 0; ks < 8; ++ks) {
            uint32_t ac = (uint32_t)((2 * ks + akh) ^ (arowl & 7));
            uint32_t aoff = (uint32_t)arowl * 256u + (ac << 4);
            uint32_t A[4];
            ldsm_x4(A, ab + aoff);
#pragma unroll
            for (int np = 0; np < NT / 2; ++np) {
                int brow = n0 + np * 16 + browl;
                uint32_t bc = (uint32_t)((2 * ks + bkh) ^ (brow & 7));
                uint32_t boff = (uint32_t)brow * 256u + (bc << 4);
                uint32_t Bh[4], Bl[4];
                ldsm_x4(Bh, wb + boff);
                ldsm_x4(Bl, wb + (uint32_t)NB + boff);
                float* a0 = acc[np * 2];
                float* a1 = acc[np * 2 + 1];
                mma_f16(a0, A, Bh);  mma_f16(a1, A, Bh + 2);
                mma_f16(a0, A, Bl);  mma_f16(a1, A, Bl + 2);
            }
        }

        const int r0 = tile * 32 + rhalf + (lane >> 2);
        const int r1 = r0 + 8;
#pragma unroll
        for (int nt = 0; nt < NT; ++nt) {
            int c = n0 + nt * 8 + (lane & 3) * 2;
            float v0 = acc[nt][0], v1 = acc[nt][1], v2 = acc[nt][2], v3 = acc[nt][3];
            if (MODE == 0) {
                v0 += breg[nt][0]; v1 += breg[nt][1];
                v2 += breg[nt][0]; v3 += breg[nt][1];
                if (r0 < n)
                    *reinterpret_cast<float2*>(outf + (size_t)r0 * NOUT + c) = make_float2(v0, v1);
                if (r1 < n)
                    *reinterpret_cast<float2*>(outf + (size_t)r1 * NOUT + c) = make_float2(v2, v3);
            } else {
                if (r0 < n) {
                    float2 s = *reinterpret_cast<const float2*>(aux + (size_t)r0 * NOUT + c);
                    v0 = fmaxf(v0 + s.x, 0.f); v1 = fmaxf(v1 + s.y, 0.f);
                    *reinterpret_cast<__half2*>(of16 + (size_t)r0 * NOUT + c) = __floats2half2_rn(v0, v1);
                }
                if (r1 < n) {
                    float2 s = *reinterpret_cast<const float2*>(aux + (size_t)r1 * NOUT + c);
                    v2 = fmaxf(v2 + s.x, 0.f); v3 = fmaxf(v3 + s.y, 0.f);
                    *reinterpret_cast<__half2*>(of16 + (size_t)r1 * NOUT + c) = __floats2half2_rn(v2, v3);
                }
            }
        }
        __syncthreads();
        buf ^= 1;
    }
}

// ---- layer-3 dual GEMM: S = X@Ws + b (fp32), P = X@Wn (fp16), A tiles loaded once ----
__global__ void __launch_bounds__(256, 1)
gemm3_dual_kernel(const __half* __restrict__ xf,
                  const __half* __restrict__ wsh, const __half* __restrict__ wsl,
                  const __half* __restrict__ wnh, const __half* __restrict__ wnl,
                  const float* __restrict__ bias, float* __restrict__ S,
                  __half* __restrict__ P, int n, int ntiles) {
    extern __shared__ char smem[];
    constexpr int NB = 64 * 256;
    constexpr int WBASE = 16384;
    const uint32_t sb = smem_to_u32(smem);
    const uint32_t wb = sb + WBASE;
    const int t = threadIdx.x, lane = t & 31, wid = t >> 5;

    load_swz(wsh, smem + WBASE,          64, t);
    load_swz(wsl, smem + WBASE + NB,     64, t);
    load_swz(wnh, smem + WBASE + 2 * NB, 64, t);
    load_swz(wnl, smem + WBASE + 3 * NB, 64, t);

    const int rhalf = (wid & 1) * 16;
    const int n0 = (wid >> 1) * 16;
    const int arowl = rhalf + (lane & 15);
    const int akh = lane >> 4;
    const int browl = ((lane >> 4) << 3) + (lane & 7);
    const int bkh = (lane >> 3) & 1;
    const int brow = n0 + browl;

    float breg[2][2];
#pragma unroll
    for (int nt = 0; nt < 2; ++nt) {
        int c = n0 + nt * 8 + (lane & 3) * 2;
        breg[nt][0] = __ldg(bias + c);
        breg[nt][1] = __ldg(bias + c + 1);
    }

    int tile = blockIdx.x, buf = 0;
    issue_1(xf, tile * 32, n, sb, t);
    CP_COMMIT();

    for (; tile < ntiles; tile += gridDim.x) {
        const int nxt = tile + gridDim.x;
        if (nxt < ntiles) {
            issue_1(xf, nxt * 32, n, sb + (uint32_t)(buf ^ 1) * 8192u, t);
            CP_COMMIT();
            CP_WAIT1();
        } else {
            CP_WAIT0();
        }
        __syncthreads();

        const uint32_t ab = sb + (uint32_t)buf * 8192u;
        float accS[2][4], accP[2][4];
#pragma unroll
        for (int q = 0; q < 2; ++q) {
            accS[q][0] = accS[q][1] = accS[q][2] = accS[q][3] = 0.f;
            accP[q][0] = accP[q][1] = accP[q][2] = accP[q][3] = 0.f;
        }

#pragma unroll
        for (int ks = 0; ks < 8; ++ks) {
            uint32_t ac = (uint32_t)((2 * ks + akh) ^ (arowl & 7));
            uint32_t aoff = (uint32_t)arowl * 256u + (ac << 4);
            uint32_t A[4];
            ldsm_x4(A, ab + aoff);
            uint32_t bc = (uint32_t)((2 * ks + bkh) ^ (brow & 7));
            uint32_t boff = (uint32_t)brow * 256u + (bc << 4);
            uint32_t Bsh[4], Bsl[4], Bnh[4], Bnl[4];
            ldsm_x4(Bsh, wb + boff);
            ldsm_x4(Bsl, wb + (uint32_t)NB + boff);
            ldsm_x4(Bnh, wb + (uint32_t)(2 * NB) + boff);
            ldsm_x4(Bnl, wb + (uint32_t)(3 * NB) + boff);
            mma_f16(accS[0], A, Bsh);  mma_f16(accS[1], A, Bsh + 2);
            mma_f16(accP[0], A, Bnh);  mma_f16(accP[1], A, Bnh + 2);
            mma_f16(accS[0], A, Bsl);  mma_f16(accS[1], A, Bsl + 2);
            mma_f16(accP[0], A, Bnl);  mma_f16(accP[1], A, Bnl + 2);
        }

        const int r0 = tile * 32 + rhalf + (lane >> 2);
        const int r1 = r0 + 8;
#pragma unroll
        for (int nt = 0; nt < 2; ++nt) {
            int c = n0 + nt * 8 + (lane & 3) * 2;
            if (r0 < n) {
                *reinterpret_cast<float2*>(S + (size_t)r0 * 64 + c) =
                    make_float2(accS[nt][0] + breg[nt][0], accS[nt][1] + breg[nt][1]);
                *reinterpret_cast<__half2*>(P + (size_t)r0 * 64 + c) =
                    __floats2half2_rn(accP[nt][0], accP[nt][1]);
            }
            if (r1 < n) {
                *reinterpret_cast<float2*>(S + (size_t)r1 * 64 + c) =
                    make_float2(accS[nt][2] + breg[nt][0], accS[nt][3] + breg[nt][1]);
                *reinterpret_cast<__half2*>(P + (size_t)r1 * 64 + c) =
                    __floats2half2_rn(accP[nt][2], accP[nt][3]);
            }
        }
        __syncthreads();
        buf ^= 1;
    }
}

// ---------------- launch ----------------
extern "C" void kernel_launch(void* const* d_in, const int* in_sizes, int n_in,
                              void* d_out, int out_size) {
    const float* x   = (const float*)d_in[0];
    const int*   src = (const int*)d_in[1];
    const int*   dst = (const int*)d_in[2];
    const float* Ws1 = (const float*)d_in[3];
    const float* b1  = (const float*)d_in[4];
    const float* Wn1 = (const float*)d_in[5];
    const float* Ws2 = (const float*)d_in[6];
    const float* b2  = (const float*)d_in[7];
    const float* Wn2 = (const float*)d_in[8];
    const float* Ws3 = (const float*)d_in[9];
    const float* b3  = (const float*)d_in[10];
    const float* Wn3 = (const float*)d_in[11];

    const int N = in_sizes[0] / DIM;
    const int E = in_sizes[1];
    float* out = (float*)d_out;

    int *deg_i, *rowptr, *csr;
    float *invdeg, *S1, *S3;
    __half *P16, *xf16, *hf16, *agg16, *wth, *wtl;
    cudaGetSymbolAddress((void**)&deg_i,  g_deg_i);
    cudaGetSymbolAddress((void**)&rowptr, g_rowptr);
    cudaGetSymbolAddress((void**)&csr,    g_csr);
    cudaGetSymbolAddress((void**)&invdeg, g_invdeg);
    cudaGetSymbolAddress((void**)&S1,     g_S1);
    cudaGetSymbolAddress((void**)&S3,     g_S3);
    cudaGetSymbolAddress((void**)&P16,    g_P16);
    cudaGetSymbolAddress((void**)&xf16,   g_xf16);
    cudaGetSymbolAddress((void**)&hf16,   g_hf16);
    cudaGetSymbolAddress((void**)&agg16,  g_agg16);
    cudaGetSymbolAddress((void**)&wth,    g_wth);
    cudaGetSymbolAddress((void**)&wtl,    g_wtl);

    // one-time host-side setup (runs on the non-captured correctness call first)
    static cudaStream_t s1 = nullptr;
    static cudaEvent_t evf, evsp, ea1;
    if (!s1) {
        cudaStreamCreateWithFlags(&s1, cudaStreamNonBlocking);
        cudaEventCreateWithFlags(&evf,  cudaEventDisableTiming);
        cudaEventCreateWithFlags(&evsp, cudaEventDisableTiming);
        cudaEventCreateWithFlags(&ea1,  cudaEventDisableTiming);
    }

    const int SMF = 32768 + 4 * 128 * 256;   // 163840 (fused layer 2)
    const int SMH = 16384 + 2 * 128 * 256;   // 81920  (half GEMMs)
    const int SM3 = 16384 + 4 * 64 * 256;    // 81920  (layer-3 dual)
    cudaFuncSetAttribute(gemm_kernel<128>,
                         cudaFuncAttributeMaxDynamicSharedMemorySize, SMF);
    cudaFuncSetAttribute(gemm_half_kernel<128, 0>,
                         cudaFuncAttributeMaxDynamicSharedMemorySize, SMH);
    cudaFuncSetAttribute(gemm_half_kernel<128, 1>,
                         cudaFuncAttributeMaxDynamicSharedMemorySize, SMH);
    cudaFuncSetAttribute(gemm3_dual_kernel,
                         cudaFuncAttributeMaxDynamicSharedMemorySize, SM3);

    const int nb_nodes = (N + 255) / 256;
    const int nb_edges = (E + 255) / 256;
    const int nb_agg   = (int)(((long long)N * 32 + 255) / 256);
    const int ntiles   = (N + 31) / 32;
    const int GRID     = 152;

    // ---- fork: s1 builds CSR while s0 does conversions; agg1 (s1) waits on the convert ----
    cudaEventRecord(evf, 0);
    cudaStreamWaitEvent(s1, evf, 0);

    zero_int_kernel<<<nb_nodes, 256, 0, s1>>>(deg_i, N);
    deg_kernel<<<nb_edges, 256, 0, s1>>>(dst, deg_i, E);
    scan_kernel<<<1, 1024, 0, s1>>>(deg_i, rowptr, invdeg, N);
    fill_csr_kernel<<<nb_edges, 256, 0, s1>>>(src, dst, rowptr, deg_i, csr, E);

    split_kernel<<<(N * DIM / 2 + 255) / 256, 256>>>(x, xf16, N * DIM / 2);
    cudaEventRecord(evsp, 0);
    wsplit_kernel<<<(81920 + 255) / 256, 256>>>(Ws1, Wn1, Ws2, Wn2, Ws3, Wn3, wth, wtl);

    cudaStreamWaitEvent(s1, evsp, 0);
    agg_kernel<<<nb_agg, 256, 0, s1>>>(xf16, rowptr, csr, invdeg, agg16, N);
    cudaEventRecord(ea1, s1);

    // s0: layer-1 self GEMM overlaps with CSR + agg1
    gemm_half_kernel<128, 0><<<GRID, 256, SMH>>>(
        xf16, wth + 0 * 16384, wtl + 0 * 16384, b1, S1, nullptr, N, ntiles);

    // ---- join: layer-1 neigh + the rest run single-stream ----
    cudaStreamWaitEvent(0, ea1, 0);
    gemm_half_kernel<128, 1><<<GRID, 256, SMH>>>(
        agg16, wth + 1 * 16384, wtl + 1 * 16384, S1, nullptr, hf16, N, ntiles);

    // Layer 2 (fused)
    agg_kernel<<<nb_agg, 256>>>(hf16, rowptr, csr, invdeg, agg16, N);
    gemm_kernel<128><<<GRID, 256, SMF>>>(
        hf16, agg16,
        wth + 2 * 16384, wtl + 2 * 16384, wth + 3 * 16384, wtl + 3 * 16384,
        b2, hf16, N, ntiles);

    // Layer 3: lin-before-mp (matches reference)
    gemm3_dual_kernel<<<GRID, 256, SM3>>>(
        hf16,
        wth + 4 * 16384, wtl + 4 * 16384, wth + 5 * 16384, wtl + 5 * 16384,
        b3, S3, P16, N, ntiles);
    aggadd_kernel<<<nb_agg, 256>>>(S3, P16, rowptr, csr, invdeg, out, N);
}